// round 1
// baseline (speedup 1.0000x reference)
#include <cuda_runtime.h>
#include <math.h>

#define N_ATOMS 30000
#define N_EDGES 480000
#define H 128
#define R 50
#define NB 3
#define NEX 64
#define CUTOFF 10.0f
#define PI_F 3.14159265358979323846f

// ---------------- device scratch (allocation-free) ----------------
__device__ float g_rbf[N_EDGES * R];   // 96 MB, computed once per launch
__device__ float g_C[N_EDGES];
__device__ float g_x[N_ATOMS * H];
__device__ float g_h[N_ATOMS * H];
__device__ float g_agg[N_ATOMS * H];

// ---------------- geometry: distances, cutoff, RBF ----------------
__global__ void geom_kernel(const float* __restrict__ pos,
                            const int* __restrict__ ei) {
    int gw = (blockIdx.x * blockDim.x + threadIdx.x) >> 5;
    int lane = threadIdx.x & 31;
    if (gw >= N_EDGES) return;
    int e = gw;
    int s = ei[e];
    int t = ei[N_EDGES + e];
    float dx = pos[3 * s + 0] - pos[3 * t + 0];
    float dy = pos[3 * s + 1] - pos[3 * t + 1];
    float dz = pos[3 * s + 2] - pos[3 * t + 2];
    float d = sqrtf(dx * dx + dy * dy + dz * dz + 1e-12f);
    if (lane == 0) {
        float C = (d < CUTOFF) ? 0.5f * (cosf(d * PI_F / CUTOFF) + 1.0f) : 0.0f;
        g_C[e] = C;
    }
    const float delta = CUTOFF / (float)(R - 1);
    const float coeff = -0.5f / (delta * delta);
    float u = d - (float)lane * delta;
    g_rbf[e * R + lane] = expf(coeff * u * u);
    if (lane < R - 32) {
        float u2 = d - (float)(lane + 32) * delta;
        g_rbf[e * R + lane + 32] = expf(coeff * u2 * u2);
    }
}

// ---------------- embedding gather ----------------
__global__ void embed_kernel(const int* __restrict__ types,
                             const float* __restrict__ emb) {
    int i = blockIdx.x * blockDim.x + threadIdx.x;
    if (i >= N_ATOMS * 32) return;
    int a = i >> 5;
    int c = i & 31;
    ((float4*)g_x)[a * 32 + c] = ((const float4*)emb)[types[a] * 32 + c];
}

// ---------------- h = x @ lin1 (no bias) ----------------
__global__ void lin1_kernel(const float* __restrict__ W) {
    extern __shared__ float sm[];
    float* Ws = sm;               // H*H
    float* xbuf = sm + H * H;     // wpb * H
    for (int i = threadIdx.x; i < H * H; i += blockDim.x) Ws[i] = W[i];
    __syncthreads();
    int lane = threadIdx.x & 31;
    int w = threadIdx.x >> 5;
    int wpb = blockDim.x >> 5;
    float* xb = xbuf + w * H;
    const float4* Ws4 = (const float4*)Ws;
    for (int a = blockIdx.x * wpb + w; a < N_ATOMS; a += gridDim.x * wpb) {
        float4 xv = ((const float4*)g_x)[a * 32 + lane];
        ((float4*)xb)[lane] = xv;
        __syncwarp();
        float ax = 0.f, ay = 0.f, az = 0.f, aw = 0.f;
#pragma unroll 4
        for (int k = 0; k < H; k++) {
            float xk = xb[k];
            float4 wv = Ws4[k * 32 + lane];
            ax = fmaf(xk, wv.x, ax); ay = fmaf(xk, wv.y, ay);
            az = fmaf(xk, wv.z, az); aw = fmaf(xk, wv.w, aw);
        }
        float4 o; o.x = ax; o.y = ay; o.z = az; o.w = aw;
        ((float4*)g_h)[a * 32 + lane] = o;
        __syncwarp();
    }
}

__global__ void zero_agg_kernel() {
    int i = blockIdx.x * blockDim.x + threadIdx.x;
    if (i < N_ATOMS * H / 4) {
        float4 z; z.x = z.y = z.z = z.w = 0.f;
        ((float4*)g_agg)[i] = z;
    }
}

// ---------------- fused edge kernel: filter net + cfconv message + scatter ----------------
__global__ void edge_kernel(const float* __restrict__ W1, const float* __restrict__ b1,
                            const float* __restrict__ W2, const float* __restrict__ b2,
                            const int* __restrict__ ei) {
    extern __shared__ float sm[];
    float* W1s = sm;                 // R*H = 6400
    float* b1s = W1s + R * H;        // 128
    float* W2s = b1s + H;            // 16384
    float* b2s = W2s + H * H;        // 128
    float* tbuf = b2s + H;           // wpb*H
    for (int i = threadIdx.x; i < R * H; i += blockDim.x) W1s[i] = W1[i];
    for (int i = threadIdx.x; i < H * H; i += blockDim.x) W2s[i] = W2[i];
    if (threadIdx.x < H) { b1s[threadIdx.x] = b1[threadIdx.x]; b2s[threadIdx.x] = b2[threadIdx.x]; }
    __syncthreads();

    int lane = threadIdx.x & 31;
    int w = threadIdx.x >> 5;
    int wpb = blockDim.x >> 5;
    float* tb = tbuf + w * H;
    const float4* W1s4 = (const float4*)W1s;
    const float4* W2s4 = (const float4*)W2s;
    float4 b14 = ((const float4*)b1s)[lane];
    float4 b24 = ((const float4*)b2s)[lane];

    for (int e = blockIdx.x * wpb + w; e < N_EDGES; e += gridDim.x * wpb) {
        float C = g_C[e];
        if (C == 0.0f) continue;   // warp-uniform: e is warp-uniform

        const float* rbf = g_rbf + e * R;
        float r0 = rbf[lane];
        float r1 = (lane < R - 32) ? rbf[lane + 32] : 0.0f;

        // stage 1: t = tanh(rbf @ W1 + b1)
        float ax = b14.x, ay = b14.y, az = b14.z, aw = b14.w;
#pragma unroll
        for (int r = 0; r < 32; r++) {
            float v = __shfl_sync(0xffffffffu, r0, r);
            float4 wv = W1s4[r * 32 + lane];
            ax = fmaf(v, wv.x, ax); ay = fmaf(v, wv.y, ay);
            az = fmaf(v, wv.z, az); aw = fmaf(v, wv.w, aw);
        }
#pragma unroll
        for (int r = 0; r < R - 32; r++) {
            float v = __shfl_sync(0xffffffffu, r1, r);
            float4 wv = W1s4[(32 + r) * 32 + lane];
            ax = fmaf(v, wv.x, ax); ay = fmaf(v, wv.y, ay);
            az = fmaf(v, wv.z, az); aw = fmaf(v, wv.w, aw);
        }
        float4 t4;
        t4.x = tanhf(ax); t4.y = tanhf(ay); t4.z = tanhf(az); t4.w = tanhf(aw);
        ((float4*)tb)[lane] = t4;
        __syncwarp();

        // stage 2: Wf = t @ W2 + b2
        float cx = b24.x, cy = b24.y, cz = b24.z, cw = b24.w;
#pragma unroll 4
        for (int k = 0; k < H; k++) {
            float tk = tb[k];
            float4 wv = W2s4[k * 32 + lane];
            cx = fmaf(tk, wv.x, cx); cy = fmaf(tk, wv.y, cy);
            cz = fmaf(tk, wv.z, cz); cw = fmaf(tk, wv.w, cw);
        }
        __syncwarp();  // done reading tb before next edge overwrites

        int s = ei[e];
        int dsti = ei[N_EDGES + e];
        float4 hv = ((const float4*)g_h)[s * 32 + lane];
        float mx = hv.x * cx * C;
        float my = hv.y * cy * C;
        float mz = hv.z * cz * C;
        float mw = hv.w * cw * C;
        float* dst = g_agg + dsti * H + lane * 4;
        atomicAdd(dst + 0, mx);
        atomicAdd(dst + 1, my);
        atomicAdd(dst + 2, mz);
        atomicAdd(dst + 3, mw);
    }
}

// ---------------- fused node update: x += tanh(agg@lin2+b) @ blk + blk_b ----------------
__global__ void update_kernel(const float* __restrict__ lin2_w, const float* __restrict__ lin2_b,
                              const float* __restrict__ blk_w, const float* __restrict__ blk_b) {
    extern __shared__ float sm[];
    float* As = sm;                  // lin2  H*H
    float* Bs = As + H * H;          // blk   H*H
    float* ab1 = Bs + H * H;         // lin2_b 128
    float* ab2 = ab1 + H;            // blk_b  128
    float* buf = ab2 + H;            // wpb*H
    for (int i = threadIdx.x; i < H * H; i += blockDim.x) { As[i] = lin2_w[i]; Bs[i] = blk_w[i]; }
    if (threadIdx.x < H) { ab1[threadIdx.x] = lin2_b[threadIdx.x]; ab2[threadIdx.x] = blk_b[threadIdx.x]; }
    __syncthreads();

    int lane = threadIdx.x & 31;
    int w = threadIdx.x >> 5;
    int wpb = blockDim.x >> 5;
    float* rb = buf + w * H;
    const float4* As4 = (const float4*)As;
    const float4* Bs4 = (const float4*)Bs;
    float4 b14 = ((const float4*)ab1)[lane];
    float4 b24 = ((const float4*)ab2)[lane];

    for (int a = blockIdx.x * wpb + w; a < N_ATOMS; a += gridDim.x * wpb) {
        float4 av = ((const float4*)g_agg)[a * 32 + lane];
        ((float4*)rb)[lane] = av;
        __syncwarp();
        float ux = b14.x, uy = b14.y, uz = b14.z, uw = b14.w;
#pragma unroll 4
        for (int k = 0; k < H; k++) {
            float rk = rb[k];
            float4 wv = As4[k * 32 + lane];
            ux = fmaf(rk, wv.x, ux); uy = fmaf(rk, wv.y, uy);
            uz = fmaf(rk, wv.z, uz); uw = fmaf(rk, wv.w, uw);
        }
        __syncwarp();
        float4 v4;
        v4.x = tanhf(ux); v4.y = tanhf(uy); v4.z = tanhf(uz); v4.w = tanhf(uw);
        ((float4*)rb)[lane] = v4;
        __syncwarp();
        float ox = b24.x, oy = b24.y, oz = b24.z, ow = b24.w;
#pragma unroll 4
        for (int k = 0; k < H; k++) {
            float vk = rb[k];
            float4 wv = Bs4[k * 32 + lane];
            ox = fmaf(vk, wv.x, ox); oy = fmaf(vk, wv.y, oy);
            oz = fmaf(vk, wv.z, oz); ow = fmaf(vk, wv.w, ow);
        }
        __syncwarp();
        float4 xv = ((const float4*)g_x)[a * 32 + lane];
        xv.x += ox; xv.y += oy; xv.z += oz; xv.w += ow;
        ((float4*)g_x)[a * 32 + lane] = xv;
    }
}

// ---------------- output head + per-molecule reduction ----------------
__global__ void zero_out_kernel(float* out) {
    if (threadIdx.x < NEX) out[threadIdx.x] = 0.0f;
}

__global__ void out_kernel(const float* __restrict__ w1, const float* __restrict__ b1v,
                           const float* __restrict__ w2, const float* __restrict__ b2v,
                           const int* __restrict__ batch, float* __restrict__ out) {
    __shared__ float w1s[H * 64];
    __shared__ float w2s[64];
    __shared__ float b1s[64];
    __shared__ float xb[8 * H];      // 256 threads = 8 warps
    for (int i = threadIdx.x; i < H * 64; i += blockDim.x) w1s[i] = w1[i];
    if (threadIdx.x < 64) { w2s[threadIdx.x] = w2[threadIdx.x]; b1s[threadIdx.x] = b1v[threadIdx.x]; }
    __syncthreads();
    float ob2 = b2v[0];
    int lane = threadIdx.x & 31;
    int w = threadIdx.x >> 5;
    int wpb = blockDim.x >> 5;
    float* rb = xb + w * H;
    for (int a = blockIdx.x * wpb + w; a < N_ATOMS; a += gridDim.x * wpb) {
        float4 xv = ((const float4*)g_x)[a * 32 + lane];
        ((float4*)rb)[lane] = xv;
        __syncwarp();
        float a0 = b1s[lane], a1 = b1s[lane + 32];
#pragma unroll 4
        for (int k = 0; k < H; k++) {
            float xk = rb[k];
            a0 = fmaf(xk, w1s[k * 64 + lane], a0);
            a1 = fmaf(xk, w1s[k * 64 + lane + 32], a1);
        }
        __syncwarp();
        float part = tanhf(a0) * w2s[lane] + tanhf(a1) * w2s[lane + 32];
#pragma unroll
        for (int off = 16; off; off >>= 1)
            part += __shfl_down_sync(0xffffffffu, part, off);
        if (lane == 0) atomicAdd(&out[batch[a]], part + ob2);
    }
}

// ---------------- host launcher ----------------
extern "C" void kernel_launch(void* const* d_in, const int* in_sizes, int n_in,
                              void* d_out, int out_size) {
    const float* pos        = (const float*)d_in[0];
    const int*   atom_types = (const int*)  d_in[1];
    const int*   edge_index = (const int*)  d_in[2];
    const int*   batch      = (const int*)  d_in[3];
    const float* embedding  = (const float*)d_in[4];
    const float* filt_w1    = (const float*)d_in[5];
    const float* filt_b1    = (const float*)d_in[6];
    const float* filt_w2    = (const float*)d_in[7];
    const float* filt_b2    = (const float*)d_in[8];
    const float* lin1_w     = (const float*)d_in[9];
    const float* lin2_w     = (const float*)d_in[10];
    const float* lin2_b     = (const float*)d_in[11];
    const float* blk_w      = (const float*)d_in[12];
    const float* blk_b      = (const float*)d_in[13];
    const float* out_w1     = (const float*)d_in[14];
    const float* out_b1     = (const float*)d_in[15];
    const float* out_w2     = (const float*)d_in[16];
    const float* out_b2     = (const float*)d_in[17];
    float* out = (float*)d_out;

    const int SM_LIN1 = (H * H + 8 * H) * 4;                     // 69632
    const int SM_EDGE = (R * H + H + H * H + H + 8 * H) * 4;     // 96256
    const int SM_UPD  = (2 * H * H + 2 * H + 16 * H) * 4;        // 140288
    cudaFuncSetAttribute(lin1_kernel,   cudaFuncAttributeMaxDynamicSharedMemorySize, SM_LIN1);
    cudaFuncSetAttribute(edge_kernel,   cudaFuncAttributeMaxDynamicSharedMemorySize, SM_EDGE);
    cudaFuncSetAttribute(update_kernel, cudaFuncAttributeMaxDynamicSharedMemorySize, SM_UPD);

    // geometry + RBF (once) and embedding
    geom_kernel<<<(N_EDGES * 32 + 255) / 256, 256>>>(pos, edge_index);
    embed_kernel<<<(N_ATOMS * 32 + 255) / 256, 256>>>(atom_types, embedding);

    for (int b = 0; b < NB; b++) {
        lin1_kernel<<<444, 256, SM_LIN1>>>(lin1_w + b * H * H);
        zero_agg_kernel<<<(N_ATOMS * H / 4 + 255) / 256, 256>>>();
        edge_kernel<<<296, 256, SM_EDGE>>>(filt_w1 + b * R * H, filt_b1 + b * H,
                                           filt_w2 + b * H * H, filt_b2 + b * H,
                                           edge_index);
        update_kernel<<<304, 512, SM_UPD>>>(lin2_w + b * H * H, lin2_b + b * H,
                                            blk_w + b * H * H, blk_b + b * H);
    }

    zero_out_kernel<<<1, 64>>>(out);
    out_kernel<<<296, 256>>>(out_w1, out_b1, out_w2, out_b2, batch, out);
}

// round 2
// speedup vs baseline: 1.3752x; 1.3752x over previous
#include <cuda_runtime.h>
#include <math.h>

#define N_ATOMS 30000
#define N_EDGES 480000
#define H 128
#define R 50
#define NB 3
#define NEX 64
#define CUTOFF 10.0f
#define PI_F 3.14159265358979323846f

#define TILE_E 128
#define N_TILES (N_EDGES / TILE_E)   // 3750 exactly
#define T_STRIDE 132                 // padded row stride for t-tile (mult of 4)
#define R_PAD 52                     // padded k for stage-1 (mult of 4)

typedef unsigned long long ull;

#define PACK2(d, x, y) asm("mov.b64 %0, {%1, %2};" : "=l"(d) : "f"(x), "f"(y))
#define UNPACK2(x, y, s) asm("mov.b64 {%0, %1}, %2;" : "=f"(x), "=f"(y) : "l"(s))
#define FMA2(d, a, b, c) asm("fma.rn.f32x2 %0, %1, %2, %3;" : "=l"(d) : "l"(a), "l"(b), "l"(c))

// ---------------- device scratch (allocation-free) ----------------
__device__ float g_rbf[N_EDGES * R];   // 96 MB, computed once per launch
__device__ float g_C[N_EDGES];
__device__ float g_x[N_ATOMS * H];
__device__ float g_h[N_ATOMS * H];
__device__ float g_agg[N_ATOMS * H];

// ---------------- geometry: distances, cutoff, RBF ----------------
__global__ void geom_kernel(const float* __restrict__ pos,
                            const int* __restrict__ ei) {
    int gw = (blockIdx.x * blockDim.x + threadIdx.x) >> 5;
    int lane = threadIdx.x & 31;
    if (gw >= N_EDGES) return;
    int e = gw;
    int s = ei[e];
    int t = ei[N_EDGES + e];
    float dx = pos[3 * s + 0] - pos[3 * t + 0];
    float dy = pos[3 * s + 1] - pos[3 * t + 1];
    float dz = pos[3 * s + 2] - pos[3 * t + 2];
    float d = sqrtf(dx * dx + dy * dy + dz * dz + 1e-12f);
    if (lane == 0) {
        float C = (d < CUTOFF) ? 0.5f * (cosf(d * PI_F / CUTOFF) + 1.0f) : 0.0f;
        g_C[e] = C;
    }
    const float delta = CUTOFF / (float)(R - 1);
    const float coeff = -0.5f / (delta * delta);
    float u = d - (float)lane * delta;
    g_rbf[e * R + lane] = expf(coeff * u * u);
    if (lane < R - 32) {
        float u2 = d - (float)(lane + 32) * delta;
        g_rbf[e * R + lane + 32] = expf(coeff * u2 * u2);
    }
}

// ---------------- embedding gather ----------------
__global__ void embed_kernel(const int* __restrict__ types,
                             const float* __restrict__ emb) {
    int i = blockIdx.x * blockDim.x + threadIdx.x;
    if (i >= N_ATOMS * 32) return;
    int a = i >> 5;
    int c = i & 31;
    ((float4*)g_x)[a * 32 + c] = ((const float4*)emb)[types[a] * 32 + c];
}

// ---------------- h = x @ lin1 (no bias) ----------------
__global__ void lin1_kernel(const float* __restrict__ W) {
    extern __shared__ float sm[];
    float* Ws = sm;               // H*H
    float* xbuf = sm + H * H;     // wpb * H
    for (int i = threadIdx.x; i < H * H; i += blockDim.x) Ws[i] = W[i];
    __syncthreads();
    int lane = threadIdx.x & 31;
    int w = threadIdx.x >> 5;
    int wpb = blockDim.x >> 5;
    float* xb = xbuf + w * H;
    const float4* Ws4 = (const float4*)Ws;
    for (int a = blockIdx.x * wpb + w; a < N_ATOMS; a += gridDim.x * wpb) {
        float4 xv = ((const float4*)g_x)[a * 32 + lane];
        ((float4*)xb)[lane] = xv;
        __syncwarp();
        float ax = 0.f, ay = 0.f, az = 0.f, aw = 0.f;
#pragma unroll 4
        for (int k = 0; k < H; k++) {
            float xk = xb[k];
            float4 wv = Ws4[k * 32 + lane];
            ax = fmaf(xk, wv.x, ax); ay = fmaf(xk, wv.y, ay);
            az = fmaf(xk, wv.z, az); aw = fmaf(xk, wv.w, aw);
        }
        float4 o; o.x = ax; o.y = ay; o.z = az; o.w = aw;
        ((float4*)g_h)[a * 32 + lane] = o;
        __syncwarp();
    }
}

__global__ void zero_agg_kernel() {
    int i = blockIdx.x * blockDim.x + threadIdx.x;
    if (i < N_ATOMS * H / 4) {
        float4 z; z.x = z.y = z.z = z.w = 0.f;
        ((float4*)g_agg)[i] = z;
    }
}

// ---------------- fused edge GEMM: filter net + cfconv message + scatter ----
// Block = 256 threads handles tiles of 128 edges. Register-tiled 8x8 micro
// tiles with packed f32x2 FMA. Thread (ty,tx): edges ty*8..+8, cols tx*8..+8.
__global__ __launch_bounds__(256) void edge_gemm_kernel(
        const float* __restrict__ W1, const float* __restrict__ b1,
        const float* __restrict__ W2, const float* __restrict__ b2,
        const int* __restrict__ ei) {
    extern __shared__ float sm[];
    float* W1s = sm;                          // R_PAD * 128
    float* W2s = W1s + R_PAD * H;             // 128 * 128
    float* b1s = W2s + H * H;                 // 128
    float* b2s = b1s + H;                     // 128
    float* tbuf = b2s + H;                    // 128 * T_STRIDE (union: rbf tile 128*R_PAD)
    float* Ce   = tbuf + TILE_E * T_STRIDE;   // 128
    int*   srcs = (int*)(Ce + TILE_E);        // 128
    int*   dsts = srcs + TILE_E;              // 128

    int tid = threadIdx.x;
    for (int i = tid; i < R_PAD * H; i += 256) W1s[i] = (i < R * H) ? W1[i] : 0.0f;
    for (int i = tid; i < H * H; i += 256) W2s[i] = W2[i];
    if (tid < H) { b1s[tid] = b1[tid]; b2s[tid] = b2[tid]; }
    __syncthreads();

    const int tx = tid & 15;
    const int ty = tid >> 4;
    const int colbase = tx * 8;
    const int rowbase = ty * 8;

    for (int tile = blockIdx.x; tile < N_TILES; tile += gridDim.x) {
        int e0 = tile * TILE_E;
        // load rbf tile as [e][R_PAD], zero-padded cols
        for (int i = tid; i < TILE_E * R_PAD; i += 256) {
            int e = i / R_PAD, r = i - e * R_PAD;
            tbuf[i] = (r < R) ? g_rbf[(e0 + e) * R + r] : 0.0f;
        }
        if (tid < TILE_E) {
            Ce[tid] = g_C[e0 + tid];
            srcs[tid] = ei[e0 + tid];
            dsts[tid] = ei[N_EDGES + e0 + tid];
        }
        __syncthreads();

        ull acc[8][4];
        // ----- stage 1: t = tanh(rbf @ W1 + b1) -----
        {
            ull binit[4];
#pragma unroll
            for (int j2 = 0; j2 < 4; j2++)
                PACK2(binit[j2], b1s[colbase + 2 * j2], b1s[colbase + 2 * j2 + 1]);
#pragma unroll
            for (int i = 0; i < 8; i++)
#pragma unroll
                for (int j2 = 0; j2 < 4; j2++) acc[i][j2] = binit[j2];
        }
        for (int k4 = 0; k4 < R_PAD / 4; k4++) {
            float4 av[8];
#pragma unroll
            for (int i = 0; i < 8; i++)
                av[i] = *(const float4*)&tbuf[(rowbase + i) * R_PAD + k4 * 4];
#pragma unroll
            for (int kk = 0; kk < 4; kk++) {
                int k = k4 * 4 + kk;
                float4 blo = *(const float4*)&W1s[k * H + colbase];
                float4 bhi = *(const float4*)&W1s[k * H + colbase + 4];
                ull bp[4];
                PACK2(bp[0], blo.x, blo.y); PACK2(bp[1], blo.z, blo.w);
                PACK2(bp[2], bhi.x, bhi.y); PACK2(bp[3], bhi.z, bhi.w);
#pragma unroll
                for (int i = 0; i < 8; i++) {
                    float a = (kk == 0) ? av[i].x : (kk == 1) ? av[i].y
                              : (kk == 2) ? av[i].z : av[i].w;
                    ull aa; PACK2(aa, a, a);
                    FMA2(acc[i][0], aa, bp[0], acc[i][0]);
                    FMA2(acc[i][1], aa, bp[1], acc[i][1]);
                    FMA2(acc[i][2], aa, bp[2], acc[i][2]);
                    FMA2(acc[i][3], aa, bp[3], acc[i][3]);
                }
            }
        }
        __syncthreads();   // all rbf reads done; tbuf reused for t
        // tanh + store t tile [e][T_STRIDE]
#pragma unroll
        for (int i = 0; i < 8; i++) {
            float v[8];
#pragma unroll
            for (int j2 = 0; j2 < 4; j2++) UNPACK2(v[2 * j2], v[2 * j2 + 1], acc[i][j2]);
#pragma unroll
            for (int j = 0; j < 8; j++) v[j] = tanhf(v[j]);
            float4 o0; o0.x = v[0]; o0.y = v[1]; o0.z = v[2]; o0.w = v[3];
            float4 o1; o1.x = v[4]; o1.y = v[5]; o1.z = v[6]; o1.w = v[7];
            *(float4*)&tbuf[(rowbase + i) * T_STRIDE + colbase] = o0;
            *(float4*)&tbuf[(rowbase + i) * T_STRIDE + colbase + 4] = o1;
        }
        __syncthreads();

        // ----- stage 2: Wf = t @ W2 + b2 -----
        {
            ull binit[4];
#pragma unroll
            for (int j2 = 0; j2 < 4; j2++)
                PACK2(binit[j2], b2s[colbase + 2 * j2], b2s[colbase + 2 * j2 + 1]);
#pragma unroll
            for (int i = 0; i < 8; i++)
#pragma unroll
                for (int j2 = 0; j2 < 4; j2++) acc[i][j2] = binit[j2];
        }
        for (int k4 = 0; k4 < H / 4; k4++) {
            float4 av[8];
#pragma unroll
            for (int i = 0; i < 8; i++)
                av[i] = *(const float4*)&tbuf[(rowbase + i) * T_STRIDE + k4 * 4];
#pragma unroll
            for (int kk = 0; kk < 4; kk++) {
                int k = k4 * 4 + kk;
                float4 blo = *(const float4*)&W2s[k * H + colbase];
                float4 bhi = *(const float4*)&W2s[k * H + colbase + 4];
                ull bp[4];
                PACK2(bp[0], blo.x, blo.y); PACK2(bp[1], blo.z, blo.w);
                PACK2(bp[2], bhi.x, bhi.y); PACK2(bp[3], bhi.z, bhi.w);
#pragma unroll
                for (int i = 0; i < 8; i++) {
                    float a = (kk == 0) ? av[i].x : (kk == 1) ? av[i].y
                              : (kk == 2) ? av[i].z : av[i].w;
                    ull aa; PACK2(aa, a, a);
                    FMA2(acc[i][0], aa, bp[0], acc[i][0]);
                    FMA2(acc[i][1], aa, bp[1], acc[i][1]);
                    FMA2(acc[i][2], aa, bp[2], acc[i][2]);
                    FMA2(acc[i][3], aa, bp[3], acc[i][3]);
                }
            }
        }

        // ----- epilogue: msg = Wf * C_e * h[src], scatter-add to agg[dst] ---
#pragma unroll
        for (int i = 0; i < 8; i++) {
            float c = Ce[rowbase + i];
            if (c != 0.0f) {
                int s = srcs[rowbase + i];
                int dd = dsts[rowbase + i];
                const float4* hp = (const float4*)(g_h + s * H + colbase);
                float4 h0 = hp[0], h1 = hp[1];
                float v[8];
#pragma unroll
                for (int j2 = 0; j2 < 4; j2++) UNPACK2(v[2 * j2], v[2 * j2 + 1], acc[i][j2]);
                float* dst = g_agg + dd * H + colbase;
                atomicAdd(dst + 0, v[0] * h0.x * c);
                atomicAdd(dst + 1, v[1] * h0.y * c);
                atomicAdd(dst + 2, v[2] * h0.z * c);
                atomicAdd(dst + 3, v[3] * h0.w * c);
                atomicAdd(dst + 4, v[4] * h1.x * c);
                atomicAdd(dst + 5, v[5] * h1.y * c);
                atomicAdd(dst + 6, v[6] * h1.z * c);
                atomicAdd(dst + 7, v[7] * h1.w * c);
            }
        }
        __syncthreads();   // tbuf reads complete before next tile overwrites
    }
}

// ---------------- fused node update: x += tanh(agg@lin2+b) @ blk + blk_b ----
__global__ void update_kernel(const float* __restrict__ lin2_w, const float* __restrict__ lin2_b,
                              const float* __restrict__ blk_w, const float* __restrict__ blk_b) {
    extern __shared__ float sm[];
    float* As = sm;                  // lin2  H*H
    float* Bs = As + H * H;          // blk   H*H
    float* ab1 = Bs + H * H;         // lin2_b 128
    float* ab2 = ab1 + H;            // blk_b  128
    float* buf = ab2 + H;            // wpb*H
    for (int i = threadIdx.x; i < H * H; i += blockDim.x) { As[i] = lin2_w[i]; Bs[i] = blk_w[i]; }
    if (threadIdx.x < H) { ab1[threadIdx.x] = lin2_b[threadIdx.x]; ab2[threadIdx.x] = blk_b[threadIdx.x]; }
    __syncthreads();

    int lane = threadIdx.x & 31;
    int w = threadIdx.x >> 5;
    int wpb = blockDim.x >> 5;
    float* rb = buf + w * H;
    const float4* As4 = (const float4*)As;
    const float4* Bs4 = (const float4*)Bs;
    float4 b14 = ((const float4*)ab1)[lane];
    float4 b24 = ((const float4*)ab2)[lane];

    for (int a = blockIdx.x * wpb + w; a < N_ATOMS; a += gridDim.x * wpb) {
        float4 av = ((const float4*)g_agg)[a * 32 + lane];
        ((float4*)rb)[lane] = av;
        __syncwarp();
        float ux = b14.x, uy = b14.y, uz = b14.z, uw = b14.w;
#pragma unroll 4
        for (int k = 0; k < H; k++) {
            float rk = rb[k];
            float4 wv = As4[k * 32 + lane];
            ux = fmaf(rk, wv.x, ux); uy = fmaf(rk, wv.y, uy);
            uz = fmaf(rk, wv.z, uz); uw = fmaf(rk, wv.w, uw);
        }
        __syncwarp();
        float4 v4;
        v4.x = tanhf(ux); v4.y = tanhf(uy); v4.z = tanhf(uz); v4.w = tanhf(uw);
        ((float4*)rb)[lane] = v4;
        __syncwarp();
        float ox = b24.x, oy = b24.y, oz = b24.z, ow = b24.w;
#pragma unroll 4
        for (int k = 0; k < H; k++) {
            float vk = rb[k];
            float4 wv = Bs4[k * 32 + lane];
            ox = fmaf(vk, wv.x, ox); oy = fmaf(vk, wv.y, oy);
            oz = fmaf(vk, wv.z, oz); ow = fmaf(vk, wv.w, ow);
        }
        __syncwarp();
        float4 xv = ((const float4*)g_x)[a * 32 + lane];
        xv.x += ox; xv.y += oy; xv.z += oz; xv.w += ow;
        ((float4*)g_x)[a * 32 + lane] = xv;
    }
}

// ---------------- output head + per-molecule reduction ----------------
__global__ void zero_out_kernel(float* out) {
    if (threadIdx.x < NEX) out[threadIdx.x] = 0.0f;
}

__global__ void out_kernel(const float* __restrict__ w1, const float* __restrict__ b1v,
                           const float* __restrict__ w2, const float* __restrict__ b2v,
                           const int* __restrict__ batch, float* __restrict__ out) {
    __shared__ float w1s[H * 64];
    __shared__ float w2s[64];
    __shared__ float b1s[64];
    __shared__ float xb[8 * H];
    for (int i = threadIdx.x; i < H * 64; i += blockDim.x) w1s[i] = w1[i];
    if (threadIdx.x < 64) { w2s[threadIdx.x] = w2[threadIdx.x]; b1s[threadIdx.x] = b1v[threadIdx.x]; }
    __syncthreads();
    float ob2 = b2v[0];
    int lane = threadIdx.x & 31;
    int w = threadIdx.x >> 5;
    int wpb = blockDim.x >> 5;
    float* rb = xb + w * H;
    for (int a = blockIdx.x * wpb + w; a < N_ATOMS; a += gridDim.x * wpb) {
        float4 xv = ((const float4*)g_x)[a * 32 + lane];
        ((float4*)rb)[lane] = xv;
        __syncwarp();
        float a0 = b1s[lane], a1 = b1s[lane + 32];
#pragma unroll 4
        for (int k = 0; k < H; k++) {
            float xk = rb[k];
            a0 = fmaf(xk, w1s[k * 64 + lane], a0);
            a1 = fmaf(xk, w1s[k * 64 + lane + 32], a1);
        }
        __syncwarp();
        float part = tanhf(a0) * w2s[lane] + tanhf(a1) * w2s[lane + 32];
#pragma unroll
        for (int off = 16; off; off >>= 1)
            part += __shfl_down_sync(0xffffffffu, part, off);
        if (lane == 0) atomicAdd(&out[batch[a]], part + ob2);
    }
}

// ---------------- host launcher ----------------
extern "C" void kernel_launch(void* const* d_in, const int* in_sizes, int n_in,
                              void* d_out, int out_size) {
    const float* pos        = (const float*)d_in[0];
    const int*   atom_types = (const int*)  d_in[1];
    const int*   edge_index = (const int*)  d_in[2];
    const int*   batch      = (const int*)  d_in[3];
    const float* embedding  = (const float*)d_in[4];
    const float* filt_w1    = (const float*)d_in[5];
    const float* filt_b1    = (const float*)d_in[6];
    const float* filt_w2    = (const float*)d_in[7];
    const float* filt_b2    = (const float*)d_in[8];
    const float* lin1_w     = (const float*)d_in[9];
    const float* lin2_w     = (const float*)d_in[10];
    const float* lin2_b     = (const float*)d_in[11];
    const float* blk_w      = (const float*)d_in[12];
    const float* blk_b      = (const float*)d_in[13];
    const float* out_w1     = (const float*)d_in[14];
    const float* out_b1     = (const float*)d_in[15];
    const float* out_w2     = (const float*)d_in[16];
    const float* out_b2     = (const float*)d_in[17];
    float* out = (float*)d_out;

    const int SM_LIN1 = (H * H + 8 * H) * 4;
    const int SM_EDGE = (R_PAD * H + H * H + 2 * H + TILE_E * T_STRIDE + TILE_E) * 4
                        + TILE_E * 2 * 4;  // 162304 bytes
    const int SM_UPD  = (2 * H * H + 2 * H + 16 * H) * 4;
    cudaFuncSetAttribute(lin1_kernel,      cudaFuncAttributeMaxDynamicSharedMemorySize, SM_LIN1);
    cudaFuncSetAttribute(edge_gemm_kernel, cudaFuncAttributeMaxDynamicSharedMemorySize, SM_EDGE);
    cudaFuncSetAttribute(update_kernel,    cudaFuncAttributeMaxDynamicSharedMemorySize, SM_UPD);

    geom_kernel<<<(N_EDGES * 32 + 255) / 256, 256>>>(pos, edge_index);
    embed_kernel<<<(N_ATOMS * 32 + 255) / 256, 256>>>(atom_types, embedding);

    for (int b = 0; b < NB; b++) {
        lin1_kernel<<<444, 256, SM_LIN1>>>(lin1_w + b * H * H);
        zero_agg_kernel<<<(N_ATOMS * H / 4 + 255) / 256, 256>>>();
        edge_gemm_kernel<<<148, 256, SM_EDGE>>>(filt_w1 + b * R * H, filt_b1 + b * H,
                                                filt_w2 + b * H * H, filt_b2 + b * H,
                                                edge_index);
        update_kernel<<<304, 512, SM_UPD>>>(lin2_w + b * H * H, lin2_b + b * H,
                                            blk_w + b * H * H, blk_b + b * H);
    }

    zero_out_kernel<<<1, 64>>>(out);
    out_kernel<<<296, 256>>>(out_w1, out_b1, out_w2, out_b2, batch, out);
}

// round 3
// speedup vs baseline: 1.8287x; 1.3298x over previous
#include <cuda_runtime.h>
#include <math.h>

#define N_ATOMS 30000
#define N_EDGES 480000
#define H 128
#define R 50
#define NB 3
#define NEX 64
#define CUTOFF 10.0f
#define PI_F 3.14159265358979323846f

#define TILE_E 128
#define N_ETILES (N_EDGES / TILE_E)                 // 3750
#define N_ATILES ((N_ATOMS + TILE_E - 1) / TILE_E)  // 235
#define T_STRIDE 132
#define R_PAD 52

typedef unsigned long long ull;

#define PACK2(d, x, y) asm("mov.b64 %0, {%1, %2};" : "=l"(d) : "f"(x), "f"(y))
#define UNPACK2(x, y, s) asm("mov.b64 {%0, %1}, %2;" : "=f"(x), "=f"(y) : "l"(s))
#define FMA2(d, a, b, c) asm("fma.rn.f32x2 %0, %1, %2, %3;" : "=l"(d) : "l"(a), "l"(b), "l"(c))
#define REDV4(p, a, b, c, d) \
    asm volatile("red.global.add.v4.f32 [%0], {%1,%2,%3,%4};" \
                 :: "l"(p), "f"(a), "f"(b), "f"(c), "f"(d) : "memory")

// ---------------- device scratch (allocation-free) ----------------
__device__ float g_d[N_EDGES];
__device__ float g_C[N_EDGES];
__device__ float g_x[N_ATOMS * H];
__device__ float g_h[N_ATOMS * H];
__device__ float g_agg[N_ATOMS * H];

// ---------------- shared 8x8 register-tile GEMM over SMEM tiles ------------
// At: [128 rows][ASTRIDE], Bm: [KDIM][H]. acc laid out as 8 rows x 4 f32x2.
template <int KDIM, int ASTRIDE>
__device__ __forceinline__ void gemm8x8(const float* __restrict__ At,
                                        const float* __restrict__ Bm,
                                        int rowbase, int colbase, ull acc[8][4]) {
    for (int k4 = 0; k4 < KDIM / 4; k4++) {
        float4 av[8];
#pragma unroll
        for (int i = 0; i < 8; i++)
            av[i] = *(const float4*)&At[(rowbase + i) * ASTRIDE + k4 * 4];
#pragma unroll
        for (int kk = 0; kk < 4; kk++) {
            int k = k4 * 4 + kk;
            float4 blo = *(const float4*)&Bm[k * H + colbase];
            float4 bhi = *(const float4*)&Bm[k * H + colbase + 4];
            ull bp[4];
            PACK2(bp[0], blo.x, blo.y); PACK2(bp[1], blo.z, blo.w);
            PACK2(bp[2], bhi.x, bhi.y); PACK2(bp[3], bhi.z, bhi.w);
#pragma unroll
            for (int i = 0; i < 8; i++) {
                float a = (kk == 0) ? av[i].x : (kk == 1) ? av[i].y
                          : (kk == 2) ? av[i].z : av[i].w;
                ull aa; PACK2(aa, a, a);
                FMA2(acc[i][0], aa, bp[0], acc[i][0]);
                FMA2(acc[i][1], aa, bp[1], acc[i][1]);
                FMA2(acc[i][2], aa, bp[2], acc[i][2]);
                FMA2(acc[i][3], aa, bp[3], acc[i][3]);
            }
        }
    }
}

__device__ __forceinline__ void init_acc(ull acc[8][4], const float* bias, int colbase) {
    ull b[4];
#pragma unroll
    for (int j = 0; j < 4; j++)
        PACK2(b[j], bias[colbase + 2 * j], bias[colbase + 2 * j + 1]);
#pragma unroll
    for (int i = 0; i < 8; i++)
#pragma unroll
        for (int j = 0; j < 4; j++) acc[i][j] = b[j];
}

__device__ __forceinline__ void init_acc_zero(ull acc[8][4]) {
#pragma unroll
    for (int i = 0; i < 8; i++)
#pragma unroll
        for (int j = 0; j < 4; j++) acc[i][j] = 0ull;
}

// ---------------- geometry: distances + cutoff only ----------------
__global__ void geom_kernel(const float* __restrict__ pos,
                            const int* __restrict__ ei) {
    int e = blockIdx.x * blockDim.x + threadIdx.x;
    if (e >= N_EDGES) return;
    int s = ei[e];
    int t = ei[N_EDGES + e];
    float dx = pos[3 * s + 0] - pos[3 * t + 0];
    float dy = pos[3 * s + 1] - pos[3 * t + 1];
    float dz = pos[3 * s + 2] - pos[3 * t + 2];
    float d = sqrtf(dx * dx + dy * dy + dz * dz + 1e-12f);
    g_d[e] = d;
    g_C[e] = (d < CUTOFF) ? 0.5f * (cosf(d * PI_F / CUTOFF) + 1.0f) : 0.0f;
}

// ---------------- embedding gather + zero agg ----------------
__global__ void embed_kernel(const int* __restrict__ types,
                             const float* __restrict__ emb) {
    int i = blockIdx.x * blockDim.x + threadIdx.x;
    if (i >= N_ATOMS * 32) return;
    int a = i >> 5;
    int c = i & 31;
    ((float4*)g_x)[a * 32 + c] = ((const float4*)emb)[types[a] * 32 + c];
    float4 z; z.x = z.y = z.z = z.w = 0.f;
    ((float4*)g_agg)[i] = z;
}

// ---------------- tiled lin1: h = x @ W (no bias) ----------------
__global__ __launch_bounds__(256) void lin1_tiled(const float* __restrict__ W) {
    extern __shared__ float sm[];
    float* Ws = sm;                  // H*H
    float* xb = Ws + H * H;          // 128 * T_STRIDE
    int tid = threadIdx.x;
    for (int i = tid; i < H * H; i += 256) Ws[i] = W[i];
    __syncthreads();
    const int tx = tid & 15, ty = tid >> 4;
    const int colbase = tx * 8, rowbase = ty * 8;

    for (int tile = blockIdx.x; tile < N_ATILES; tile += gridDim.x) {
        int a0 = tile * TILE_E;
        for (int i = tid; i < TILE_E * 32; i += 256) {
            int row = i >> 5, c = i & 31;
            float4 v; v.x = v.y = v.z = v.w = 0.f;
            if (a0 + row < N_ATOMS) v = ((const float4*)g_x)[(a0 + row) * 32 + c];
            *(float4*)&xb[row * T_STRIDE + c * 4] = v;
        }
        __syncthreads();
        ull acc[8][4];
        init_acc_zero(acc);
        gemm8x8<H, T_STRIDE>(xb, Ws, rowbase, colbase, acc);
#pragma unroll
        for (int i = 0; i < 8; i++) {
            int a = a0 + rowbase + i;
            if (a < N_ATOMS) {
                float v[8];
#pragma unroll
                for (int j = 0; j < 4; j++) UNPACK2(v[2 * j], v[2 * j + 1], acc[i][j]);
                float4 o0; o0.x = v[0]; o0.y = v[1]; o0.z = v[2]; o0.w = v[3];
                float4 o1; o1.x = v[4]; o1.y = v[5]; o1.z = v[6]; o1.w = v[7];
                *(float4*)&g_h[a * H + colbase] = o0;
                *(float4*)&g_h[a * H + colbase + 4] = o1;
            }
        }
        __syncthreads();
    }
}

// ---------------- fused edge GEMM: rbf + filter net + message + scatter ----
__global__ __launch_bounds__(256) void edge_gemm_kernel(
        const float* __restrict__ W1, const float* __restrict__ b1,
        const float* __restrict__ W2, const float* __restrict__ b2,
        const int* __restrict__ ei) {
    extern __shared__ float sm[];
    float* W1s = sm;                          // R_PAD * H
    float* W2s = W1s + R_PAD * H;             // H * H
    float* b1s = W2s + H * H;                 // H
    float* b2s = b1s + H;                     // H
    float* tbuf = b2s + H;                    // 128*T_STRIDE (rbf tile uses stride R_PAD)
    float* Ce   = tbuf + TILE_E * T_STRIDE;   // 128
    int*   srcs = (int*)(Ce + TILE_E);        // 128
    int*   dsts = srcs + TILE_E;              // 128

    int tid = threadIdx.x;
    for (int i = tid; i < R_PAD * H; i += 256) W1s[i] = (i < R * H) ? W1[i] : 0.0f;
    for (int i = tid; i < H * H; i += 256) W2s[i] = W2[i];
    if (tid < H) { b1s[tid] = b1[tid]; b2s[tid] = b2[tid]; }
    __syncthreads();

    const int tx = tid & 15, ty = tid >> 4;
    const int colbase = tx * 8, rowbase = ty * 8;
    const float delta = CUTOFF / (float)(R - 1);
    const float coeff = -0.5f / (delta * delta);

    for (int tile = blockIdx.x; tile < N_ETILES; tile += gridDim.x) {
        int e0 = tile * TILE_E;
        // build rbf tile [e][R_PAD] in smem (compute from d)
        for (int i = tid; i < TILE_E * R_PAD; i += 256) {
            int e = i / R_PAD, r = i - e * R_PAD;
            float v = 0.0f;
            if (r < R) {
                float u = g_d[e0 + e] - (float)r * delta;
                v = expf(coeff * u * u);
            }
            tbuf[i] = v;
        }
        if (tid < TILE_E) {
            Ce[tid] = g_C[e0 + tid];
            srcs[tid] = ei[e0 + tid];
            dsts[tid] = ei[N_EDGES + e0 + tid];
        }
        __syncthreads();

        ull acc[8][4];
        // stage 1: t = tanh(rbf @ W1 + b1)
        init_acc(acc, b1s, colbase);
        gemm8x8<R_PAD, R_PAD>(tbuf, W1s, rowbase, colbase, acc);
        __syncthreads();
#pragma unroll
        for (int i = 0; i < 8; i++) {
            float v[8];
#pragma unroll
            for (int j = 0; j < 4; j++) UNPACK2(v[2 * j], v[2 * j + 1], acc[i][j]);
#pragma unroll
            for (int j = 0; j < 8; j++) v[j] = tanhf(v[j]);
            float4 o0; o0.x = v[0]; o0.y = v[1]; o0.z = v[2]; o0.w = v[3];
            float4 o1; o1.x = v[4]; o1.y = v[5]; o1.z = v[6]; o1.w = v[7];
            *(float4*)&tbuf[(rowbase + i) * T_STRIDE + colbase] = o0;
            *(float4*)&tbuf[(rowbase + i) * T_STRIDE + colbase + 4] = o1;
        }
        __syncthreads();

        // stage 2: Wf = t @ W2 + b2
        init_acc(acc, b2s, colbase);
        gemm8x8<H, T_STRIDE>(tbuf, W2s, rowbase, colbase, acc);

        // epilogue: msg = Wf * C * h[src]; vector scatter-add to agg[dst]
#pragma unroll
        for (int i = 0; i < 8; i++) {
            float c = Ce[rowbase + i];
            if (c != 0.0f) {
                int s = srcs[rowbase + i];
                int dd = dsts[rowbase + i];
                const float4* hp = (const float4*)(g_h + s * H + colbase);
                float4 h0 = hp[0], h1 = hp[1];
                float v[8];
#pragma unroll
                for (int j = 0; j < 4; j++) UNPACK2(v[2 * j], v[2 * j + 1], acc[i][j]);
                float* dst = g_agg + dd * H + colbase;
                REDV4(dst,     v[0] * h0.x * c, v[1] * h0.y * c,
                               v[2] * h0.z * c, v[3] * h0.w * c);
                REDV4(dst + 4, v[4] * h1.x * c, v[5] * h1.y * c,
                               v[6] * h1.z * c, v[7] * h1.w * c);
            }
        }
        __syncthreads();
    }
}

// ------- tiled node update: x += tanh(agg@lin2+b1) @ blk + b2; rezero agg ---
__global__ __launch_bounds__(256) void update_tiled(
        const float* __restrict__ lin2_w, const float* __restrict__ lin2_b,
        const float* __restrict__ blk_w, const float* __restrict__ blk_b) {
    extern __shared__ float sm[];
    float* As = sm;                 // H*H
    float* Bs = As + H * H;         // H*H
    float* b1s = Bs + H * H;        // H
    float* b2s = b1s + H;           // H
    float* buf = b2s + H;           // 128*T_STRIDE
    int tid = threadIdx.x;
    for (int i = tid; i < H * H; i += 256) { As[i] = lin2_w[i]; Bs[i] = blk_w[i]; }
    if (tid < H) { b1s[tid] = lin2_b[tid]; b2s[tid] = blk_b[tid]; }
    __syncthreads();

    const int tx = tid & 15, ty = tid >> 4;
    const int colbase = tx * 8, rowbase = ty * 8;

    for (int tile = blockIdx.x; tile < N_ATILES; tile += gridDim.x) {
        int a0 = tile * TILE_E;
        for (int i = tid; i < TILE_E * 32; i += 256) {
            int row = i >> 5, c = i & 31;
            float4 v; v.x = v.y = v.z = v.w = 0.f;
            if (a0 + row < N_ATOMS) {
                v = ((const float4*)g_agg)[(a0 + row) * 32 + c];
                float4 z; z.x = z.y = z.z = z.w = 0.f;
                ((float4*)g_agg)[(a0 + row) * 32 + c] = z;   // rezero for next block
            }
            *(float4*)&buf[row * T_STRIDE + c * 4] = v;
        }
        __syncthreads();

        ull acc[8][4];
        init_acc(acc, b1s, colbase);
        gemm8x8<H, T_STRIDE>(buf, As, rowbase, colbase, acc);
        __syncthreads();
#pragma unroll
        for (int i = 0; i < 8; i++) {
            float v[8];
#pragma unroll
            for (int j = 0; j < 4; j++) UNPACK2(v[2 * j], v[2 * j + 1], acc[i][j]);
#pragma unroll
            for (int j = 0; j < 8; j++) v[j] = tanhf(v[j]);
            float4 o0; o0.x = v[0]; o0.y = v[1]; o0.z = v[2]; o0.w = v[3];
            float4 o1; o1.x = v[4]; o1.y = v[5]; o1.z = v[6]; o1.w = v[7];
            *(float4*)&buf[(rowbase + i) * T_STRIDE + colbase] = o0;
            *(float4*)&buf[(rowbase + i) * T_STRIDE + colbase + 4] = o1;
        }
        __syncthreads();

        init_acc(acc, b2s, colbase);
        gemm8x8<H, T_STRIDE>(buf, Bs, rowbase, colbase, acc);

#pragma unroll
        for (int i = 0; i < 8; i++) {
            int a = a0 + rowbase + i;
            if (a < N_ATOMS) {
                float v[8];
#pragma unroll
                for (int j = 0; j < 4; j++) UNPACK2(v[2 * j], v[2 * j + 1], acc[i][j]);
                float4 x0 = *(const float4*)&g_x[a * H + colbase];
                float4 x1 = *(const float4*)&g_x[a * H + colbase + 4];
                x0.x += v[0]; x0.y += v[1]; x0.z += v[2]; x0.w += v[3];
                x1.x += v[4]; x1.y += v[5]; x1.z += v[6]; x1.w += v[7];
                *(float4*)&g_x[a * H + colbase] = x0;
                *(float4*)&g_x[a * H + colbase + 4] = x1;
            }
        }
        __syncthreads();
    }
}

// ---------------- output head + per-molecule reduction ----------------
__global__ void zero_out_kernel(float* out) {
    if (threadIdx.x < NEX) out[threadIdx.x] = 0.0f;
}

__global__ void out_kernel(const float* __restrict__ w1, const float* __restrict__ b1v,
                           const float* __restrict__ w2, const float* __restrict__ b2v,
                           const int* __restrict__ batch, float* __restrict__ out) {
    __shared__ float w1s[H * 64];
    __shared__ float w2s[64];
    __shared__ float b1s[64];
    __shared__ float xb[8 * H];
    for (int i = threadIdx.x; i < H * 64; i += blockDim.x) w1s[i] = w1[i];
    if (threadIdx.x < 64) { w2s[threadIdx.x] = w2[threadIdx.x]; b1s[threadIdx.x] = b1v[threadIdx.x]; }
    __syncthreads();
    float ob2 = b2v[0];
    int lane = threadIdx.x & 31;
    int w = threadIdx.x >> 5;
    int wpb = blockDim.x >> 5;
    float* rb = xb + w * H;
    for (int a = blockIdx.x * wpb + w; a < N_ATOMS; a += gridDim.x * wpb) {
        float4 xv = ((const float4*)g_x)[a * 32 + lane];
        ((float4*)rb)[lane] = xv;
        __syncwarp();
        float a0 = b1s[lane], a1 = b1s[lane + 32];
#pragma unroll 4
        for (int k = 0; k < H; k++) {
            float xk = rb[k];
            a0 = fmaf(xk, w1s[k * 64 + lane], a0);
            a1 = fmaf(xk, w1s[k * 64 + lane + 32], a1);
        }
        __syncwarp();
        float part = tanhf(a0) * w2s[lane] + tanhf(a1) * w2s[lane + 32];
#pragma unroll
        for (int off = 16; off; off >>= 1)
            part += __shfl_down_sync(0xffffffffu, part, off);
        if (lane == 0) atomicAdd(&out[batch[a]], part + ob2);
    }
}

// ---------------- host launcher ----------------
extern "C" void kernel_launch(void* const* d_in, const int* in_sizes, int n_in,
                              void* d_out, int out_size) {
    const float* pos        = (const float*)d_in[0];
    const int*   atom_types = (const int*)  d_in[1];
    const int*   edge_index = (const int*)  d_in[2];
    const int*   batch      = (const int*)  d_in[3];
    const float* embedding  = (const float*)d_in[4];
    const float* filt_w1    = (const float*)d_in[5];
    const float* filt_b1    = (const float*)d_in[6];
    const float* filt_w2    = (const float*)d_in[7];
    const float* filt_b2    = (const float*)d_in[8];
    const float* lin1_w     = (const float*)d_in[9];
    const float* lin2_w     = (const float*)d_in[10];
    const float* lin2_b     = (const float*)d_in[11];
    const float* blk_w      = (const float*)d_in[12];
    const float* blk_b      = (const float*)d_in[13];
    const float* out_w1     = (const float*)d_in[14];
    const float* out_b1     = (const float*)d_in[15];
    const float* out_w2     = (const float*)d_in[16];
    const float* out_b2     = (const float*)d_in[17];
    float* out = (float*)d_out;

    const int SM_LIN1 = (H * H + TILE_E * T_STRIDE) * 4;                      // 133120
    const int SM_EDGE = (R_PAD * H + H * H + 2 * H + TILE_E * T_STRIDE + TILE_E) * 4
                        + TILE_E * 2 * 4;                                     // 162304
    const int SM_UPD  = (2 * H * H + 2 * H + TILE_E * T_STRIDE) * 4;          // 199680
    cudaFuncSetAttribute(lin1_tiled,       cudaFuncAttributeMaxDynamicSharedMemorySize, SM_LIN1);
    cudaFuncSetAttribute(edge_gemm_kernel, cudaFuncAttributeMaxDynamicSharedMemorySize, SM_EDGE);
    cudaFuncSetAttribute(update_tiled,     cudaFuncAttributeMaxDynamicSharedMemorySize, SM_UPD);

    geom_kernel<<<(N_EDGES + 255) / 256, 256>>>(pos, edge_index);
    embed_kernel<<<(N_ATOMS * 32 + 255) / 256, 256>>>(atom_types, embedding);

    for (int b = 0; b < NB; b++) {
        lin1_tiled<<<148, 256, SM_LIN1>>>(lin1_w + b * H * H);
        edge_gemm_kernel<<<148, 256, SM_EDGE>>>(filt_w1 + b * R * H, filt_b1 + b * H,
                                                filt_w2 + b * H * H, filt_b2 + b * H,
                                                edge_index);
        update_tiled<<<148, 256, SM_UPD>>>(lin2_w + b * H * H, lin2_b + b * H,
                                           blk_w + b * H * H, blk_b + b * H);
    }

    zero_out_kernel<<<1, 64>>>(out);
    out_kernel<<<296, 256>>>(out_w1, out_b1, out_w2, out_b2, batch, out);
}

// round 4
// speedup vs baseline: 2.0340x; 1.1122x over previous
#include <cuda_runtime.h>
#include <math.h>

#define N_ATOMS 30000
#define N_EDGES 480000
#define H 128
#define R 50
#define NB 3
#define NEX 64
#define CUTOFF 10.0f
#define PI_F 3.14159265358979323846f

#define TILE_A 128
#define N_ATILES ((N_ATOMS + TILE_A - 1) / TILE_A)  // 235
#define ETILE 192
#define N_ETILES (N_EDGES / ETILE)                  // 2500 exactly
#define T_STRIDE 132
#define R_PAD 52

typedef unsigned long long ull;

#define PACK2(d, x, y) asm("mov.b64 %0, {%1, %2};" : "=l"(d) : "f"(x), "f"(y))
#define UNPACK2(x, y, s) asm("mov.b64 {%0, %1}, %2;" : "=f"(x), "=f"(y) : "l"(s))
#define FMA2(d, a, b, c) asm("fma.rn.f32x2 %0, %1, %2, %3;" : "=l"(d) : "l"(a), "l"(b), "l"(c))
#define REDV4(p, a, b, c, d) \
    asm volatile("red.global.add.v4.f32 [%0], {%1,%2,%3,%4};" \
                 :: "l"(p), "f"(a), "f"(b), "f"(c), "f"(d) : "memory")

// ---------------- device scratch (allocation-free) ----------------
__device__ float g_d[N_EDGES];
__device__ float g_C[N_EDGES];
__device__ float g_x[N_ATOMS * H];
__device__ float g_h[N_ATOMS * H];
__device__ float g_agg[N_ATOMS * H];

// ---------------- shared 8x8 register-tile GEMM over SMEM tiles ------------
template <int KDIM, int ASTRIDE>
__device__ __forceinline__ void gemm8x8(const float* __restrict__ At,
                                        const float* __restrict__ Bm,
                                        int rowbase, int colbase, ull acc[8][4]) {
    for (int k4 = 0; k4 < KDIM / 4; k4++) {
        float4 av[8];
#pragma unroll
        for (int i = 0; i < 8; i++)
            av[i] = *(const float4*)&At[(rowbase + i) * ASTRIDE + k4 * 4];
#pragma unroll
        for (int kk = 0; kk < 4; kk++) {
            int k = k4 * 4 + kk;
            float4 blo = *(const float4*)&Bm[k * H + colbase];
            float4 bhi = *(const float4*)&Bm[k * H + colbase + 4];
            ull bp[4];
            PACK2(bp[0], blo.x, blo.y); PACK2(bp[1], blo.z, blo.w);
            PACK2(bp[2], bhi.x, bhi.y); PACK2(bp[3], bhi.z, bhi.w);
#pragma unroll
            for (int i = 0; i < 8; i++) {
                float a = (kk == 0) ? av[i].x : (kk == 1) ? av[i].y
                          : (kk == 2) ? av[i].z : av[i].w;
                ull aa; PACK2(aa, a, a);
                FMA2(acc[i][0], aa, bp[0], acc[i][0]);
                FMA2(acc[i][1], aa, bp[1], acc[i][1]);
                FMA2(acc[i][2], aa, bp[2], acc[i][2]);
                FMA2(acc[i][3], aa, bp[3], acc[i][3]);
            }
        }
    }
}

__device__ __forceinline__ void init_acc(ull acc[8][4], const float* bias, int colbase) {
    ull b[4];
#pragma unroll
    for (int j = 0; j < 4; j++)
        PACK2(b[j], bias[colbase + 2 * j], bias[colbase + 2 * j + 1]);
#pragma unroll
    for (int i = 0; i < 8; i++)
#pragma unroll
        for (int j = 0; j < 4; j++) acc[i][j] = b[j];
}

__device__ __forceinline__ void init_acc_zero(ull acc[8][4]) {
#pragma unroll
    for (int i = 0; i < 8; i++)
#pragma unroll
        for (int j = 0; j < 4; j++) acc[i][j] = 0ull;
}

// ---------------- geometry: distances + cutoff only ----------------
__global__ void geom_kernel(const float* __restrict__ pos,
                            const int* __restrict__ ei) {
    int e = blockIdx.x * blockDim.x + threadIdx.x;
    if (e >= N_EDGES) return;
    int s = ei[e];
    int t = ei[N_EDGES + e];
    float dx = pos[3 * s + 0] - pos[3 * t + 0];
    float dy = pos[3 * s + 1] - pos[3 * t + 1];
    float dz = pos[3 * s + 2] - pos[3 * t + 2];
    float d = sqrtf(dx * dx + dy * dy + dz * dz + 1e-12f);
    g_d[e] = d;
    g_C[e] = (d < CUTOFF) ? 0.5f * (cosf(d * PI_F / CUTOFF) + 1.0f) : 0.0f;
}

// ---------------- embedding gather + zero agg ----------------
__global__ void embed_kernel(const int* __restrict__ types,
                             const float* __restrict__ emb) {
    int i = blockIdx.x * blockDim.x + threadIdx.x;
    if (i >= N_ATOMS * 32) return;
    int a = i >> 5;
    int c = i & 31;
    ((float4*)g_x)[a * 32 + c] = ((const float4*)emb)[types[a] * 32 + c];
    float4 z; z.x = z.y = z.z = z.w = 0.f;
    ((float4*)g_agg)[i] = z;
}

// ---------------- tiled lin1: h = x @ W (no bias) ----------------
__global__ __launch_bounds__(256) void lin1_tiled(const float* __restrict__ W) {
    extern __shared__ float sm[];
    float* Ws = sm;                  // H*H
    float* xb = Ws + H * H;          // TILE_A * T_STRIDE
    int tid = threadIdx.x;
    for (int i = tid; i < H * H; i += 256) Ws[i] = W[i];
    __syncthreads();
    const int tx = tid & 15, ty = tid >> 4;
    const int colbase = tx * 8, rowbase = ty * 8;

    int a0 = blockIdx.x * TILE_A;
    for (int i = tid; i < TILE_A * 32; i += 256) {
        int row = i >> 5, c = i & 31;
        float4 v; v.x = v.y = v.z = v.w = 0.f;
        if (a0 + row < N_ATOMS) v = ((const float4*)g_x)[(a0 + row) * 32 + c];
        *(float4*)&xb[row * T_STRIDE + c * 4] = v;
    }
    __syncthreads();
    ull acc[8][4];
    init_acc_zero(acc);
    gemm8x8<H, T_STRIDE>(xb, Ws, rowbase, colbase, acc);
#pragma unroll
    for (int i = 0; i < 8; i++) {
        int a = a0 + rowbase + i;
        if (a < N_ATOMS) {
            float v[8];
#pragma unroll
            for (int j = 0; j < 4; j++) UNPACK2(v[2 * j], v[2 * j + 1], acc[i][j]);
            float4 o0; o0.x = v[0]; o0.y = v[1]; o0.z = v[2]; o0.w = v[3];
            float4 o1; o1.x = v[4]; o1.y = v[5]; o1.z = v[6]; o1.w = v[7];
            *(float4*)&g_h[a * H + colbase] = o0;
            *(float4*)&g_h[a * H + colbase + 4] = o1;
        }
    }
}

// ---------------- fused edge GEMM: rbf + filter net + message + scatter ----
// 384 threads, 192-edge x 128-col tile, 8x8 register micro-tiles.
__global__ __launch_bounds__(384) void edge_gemm_kernel(
        const float* __restrict__ W1, const float* __restrict__ b1,
        const float* __restrict__ W2, const float* __restrict__ b2,
        const int* __restrict__ ei) {
    extern __shared__ float sm[];
    float* W1s = sm;                          // R_PAD * H
    float* W2s = W1s + R_PAD * H;             // H * H
    float* b1s = W2s + H * H;                 // H
    float* b2s = b1s + H;                     // H
    float* tbuf = b2s + H;                    // ETILE*T_STRIDE (rbf tile: stride R_PAD)
    float* Ce   = tbuf + ETILE * T_STRIDE;    // ETILE
    int*   srcs = (int*)(Ce + ETILE);         // ETILE
    int*   dsts = srcs + ETILE;               // ETILE

    int tid = threadIdx.x;
    for (int i = tid; i < R_PAD * H; i += 384) W1s[i] = (i < R * H) ? W1[i] : 0.0f;
    for (int i = tid; i < H * H; i += 384) W2s[i] = W2[i];
    if (tid < H) { b1s[tid] = b1[tid]; b2s[tid] = b2[tid]; }
    __syncthreads();

    const int tx = tid & 15, ty = tid >> 4;   // tx 0..15, ty 0..23
    const int colbase = tx * 8, rowbase = ty * 8;
    const float delta = CUTOFF / (float)(R - 1);
    const float coeff = -0.5f / (delta * delta);

    for (int tile = blockIdx.x; tile < N_ETILES; tile += gridDim.x) {
        int e0 = tile * ETILE;
        // build rbf tile [e][R_PAD] in smem from distances
        for (int i = tid; i < ETILE * R_PAD; i += 384) {
            int e = i / R_PAD, r = i - e * R_PAD;
            float v = 0.0f;
            if (r < R) {
                float u = g_d[e0 + e] - (float)r * delta;
                v = expf(coeff * u * u);
            }
            tbuf[i] = v;
        }
        if (tid < ETILE) {
            Ce[tid] = g_C[e0 + tid];
            srcs[tid] = ei[e0 + tid];
            dsts[tid] = ei[N_EDGES + e0 + tid];
        }
        __syncthreads();

        ull acc[8][4];
        // stage 1: t = tanh(rbf @ W1 + b1)
        init_acc(acc, b1s, colbase);
        gemm8x8<R_PAD, R_PAD>(tbuf, W1s, rowbase, colbase, acc);
        __syncthreads();
#pragma unroll
        for (int i = 0; i < 8; i++) {
            float v[8];
#pragma unroll
            for (int j = 0; j < 4; j++) UNPACK2(v[2 * j], v[2 * j + 1], acc[i][j]);
#pragma unroll
            for (int j = 0; j < 8; j++) v[j] = tanhf(v[j]);
            float4 o0; o0.x = v[0]; o0.y = v[1]; o0.z = v[2]; o0.w = v[3];
            float4 o1; o1.x = v[4]; o1.y = v[5]; o1.z = v[6]; o1.w = v[7];
            *(float4*)&tbuf[(rowbase + i) * T_STRIDE + colbase] = o0;
            *(float4*)&tbuf[(rowbase + i) * T_STRIDE + colbase + 4] = o1;
        }
        __syncthreads();

        // stage 2: Wf = t @ W2 + b2
        init_acc(acc, b2s, colbase);
        gemm8x8<H, T_STRIDE>(tbuf, W2s, rowbase, colbase, acc);

        // epilogue: msg = Wf * C * h[src]; vector scatter-add to agg[dst]
#pragma unroll
        for (int i = 0; i < 8; i++) {
            float c = Ce[rowbase + i];
            if (c != 0.0f) {
                int s = srcs[rowbase + i];
                int dd = dsts[rowbase + i];
                const float4* hp = (const float4*)(g_h + s * H + colbase);
                float4 h0 = hp[0], h1 = hp[1];
                float v[8];
#pragma unroll
                for (int j = 0; j < 4; j++) UNPACK2(v[2 * j], v[2 * j + 1], acc[i][j]);
                float* dst = g_agg + dd * H + colbase;
                REDV4(dst,     v[0] * h0.x * c, v[1] * h0.y * c,
                               v[2] * h0.z * c, v[3] * h0.w * c);
                REDV4(dst + 4, v[4] * h1.x * c, v[5] * h1.y * c,
                               v[6] * h1.z * c, v[7] * h1.w * c);
            }
        }
        __syncthreads();
    }
}

// ------- tiled node update: x += tanh(agg@lin2+b1) @ blk + b2; rezero agg ---
__global__ __launch_bounds__(256) void update_tiled(
        const float* __restrict__ lin2_w, const float* __restrict__ lin2_b,
        const float* __restrict__ blk_w, const float* __restrict__ blk_b) {
    extern __shared__ float sm[];
    float* As = sm;                 // H*H
    float* Bs = As + H * H;         // H*H
    float* b1s = Bs + H * H;        // H
    float* b2s = b1s + H;           // H
    float* buf = b2s + H;           // TILE_A*T_STRIDE
    int tid = threadIdx.x;
    for (int i = tid; i < H * H; i += 256) { As[i] = lin2_w[i]; Bs[i] = blk_w[i]; }
    if (tid < H) { b1s[tid] = lin2_b[tid]; b2s[tid] = blk_b[tid]; }
    __syncthreads();

    const int tx = tid & 15, ty = tid >> 4;
    const int colbase = tx * 8, rowbase = ty * 8;

    int a0 = blockIdx.x * TILE_A;
    for (int i = tid; i < TILE_A * 32; i += 256) {
        int row = i >> 5, c = i & 31;
        float4 v; v.x = v.y = v.z = v.w = 0.f;
        if (a0 + row < N_ATOMS) {
            v = ((const float4*)g_agg)[(a0 + row) * 32 + c];
            float4 z; z.x = z.y = z.z = z.w = 0.f;
            ((float4*)g_agg)[(a0 + row) * 32 + c] = z;   // rezero for next block
        }
        *(float4*)&buf[row * T_STRIDE + c * 4] = v;
    }
    __syncthreads();

    ull acc[8][4];
    init_acc(acc, b1s, colbase);
    gemm8x8<H, T_STRIDE>(buf, As, rowbase, colbase, acc);
    __syncthreads();
#pragma unroll
    for (int i = 0; i < 8; i++) {
        float v[8];
#pragma unroll
        for (int j = 0; j < 4; j++) UNPACK2(v[2 * j], v[2 * j + 1], acc[i][j]);
#pragma unroll
        for (int j = 0; j < 8; j++) v[j] = tanhf(v[j]);
        float4 o0; o0.x = v[0]; o0.y = v[1]; o0.z = v[2]; o0.w = v[3];
        float4 o1; o1.x = v[4]; o1.y = v[5]; o1.z = v[6]; o1.w = v[7];
        *(float4*)&buf[(rowbase + i) * T_STRIDE + colbase] = o0;
        *(float4*)&buf[(rowbase + i) * T_STRIDE + colbase + 4] = o1;
    }
    __syncthreads();

    init_acc(acc, b2s, colbase);
    gemm8x8<H, T_STRIDE>(buf, Bs, rowbase, colbase, acc);

#pragma unroll
    for (int i = 0; i < 8; i++) {
        int a = a0 + rowbase + i;
        if (a < N_ATOMS) {
            float v[8];
#pragma unroll
            for (int j = 0; j < 4; j++) UNPACK2(v[2 * j], v[2 * j + 1], acc[i][j]);
            float4 x0 = *(const float4*)&g_x[a * H + colbase];
            float4 x1 = *(const float4*)&g_x[a * H + colbase + 4];
            x0.x += v[0]; x0.y += v[1]; x0.z += v[2]; x0.w += v[3];
            x1.x += v[4]; x1.y += v[5]; x1.z += v[6]; x1.w += v[7];
            *(float4*)&g_x[a * H + colbase] = x0;
            *(float4*)&g_x[a * H + colbase + 4] = x1;
        }
    }
}

// ---------------- output head + per-molecule reduction ----------------
__global__ void zero_out_kernel(float* out) {
    if (threadIdx.x < NEX) out[threadIdx.x] = 0.0f;
}

__global__ void out_kernel(const float* __restrict__ w1, const float* __restrict__ b1v,
                           const float* __restrict__ w2, const float* __restrict__ b2v,
                           const int* __restrict__ batch, float* __restrict__ out) {
    __shared__ float w1s[H * 64];
    __shared__ float w2s[64];
    __shared__ float b1s[64];
    __shared__ float xb[8 * H];
    for (int i = threadIdx.x; i < H * 64; i += blockDim.x) w1s[i] = w1[i];
    if (threadIdx.x < 64) { w2s[threadIdx.x] = w2[threadIdx.x]; b1s[threadIdx.x] = b1v[threadIdx.x]; }
    __syncthreads();
    float ob2 = b2v[0];
    int lane = threadIdx.x & 31;
    int w = threadIdx.x >> 5;
    int wpb = blockDim.x >> 5;
    float* rb = xb + w * H;
    for (int a = blockIdx.x * wpb + w; a < N_ATOMS; a += gridDim.x * wpb) {
        float4 xv = ((const float4*)g_x)[a * 32 + lane];
        ((float4*)rb)[lane] = xv;
        __syncwarp();
        float a0 = b1s[lane], a1 = b1s[lane + 32];
#pragma unroll 4
        for (int k = 0; k < H; k++) {
            float xk = rb[k];
            a0 = fmaf(xk, w1s[k * 64 + lane], a0);
            a1 = fmaf(xk, w1s[k * 64 + lane + 32], a1);
        }
        __syncwarp();
        float part = tanhf(a0) * w2s[lane] + tanhf(a1) * w2s[lane + 32];
#pragma unroll
        for (int off = 16; off; off >>= 1)
            part += __shfl_down_sync(0xffffffffu, part, off);
        if (lane == 0) atomicAdd(&out[batch[a]], part + ob2);
    }
}

// ---------------- host launcher ----------------
extern "C" void kernel_launch(void* const* d_in, const int* in_sizes, int n_in,
                              void* d_out, int out_size) {
    const float* pos        = (const float*)d_in[0];
    const int*   atom_types = (const int*)  d_in[1];
    const int*   edge_index = (const int*)  d_in[2];
    const int*   batch      = (const int*)  d_in[3];
    const float* embedding  = (const float*)d_in[4];
    const float* filt_w1    = (const float*)d_in[5];
    const float* filt_b1    = (const float*)d_in[6];
    const float* filt_w2    = (const float*)d_in[7];
    const float* filt_b2    = (const float*)d_in[8];
    const float* lin1_w     = (const float*)d_in[9];
    const float* lin2_w     = (const float*)d_in[10];
    const float* lin2_b     = (const float*)d_in[11];
    const float* blk_w      = (const float*)d_in[12];
    const float* blk_b      = (const float*)d_in[13];
    const float* out_w1     = (const float*)d_in[14];
    const float* out_b1     = (const float*)d_in[15];
    const float* out_w2     = (const float*)d_in[16];
    const float* out_b2     = (const float*)d_in[17];
    float* out = (float*)d_out;

    const int SM_LIN1 = (H * H + TILE_A * T_STRIDE) * 4;
    const int SM_EDGE = (R_PAD * H + H * H + 2 * H + ETILE * T_STRIDE + ETILE) * 4
                        + ETILE * 2 * 4;   // ~197 KB
    const int SM_UPD  = (2 * H * H + 2 * H + TILE_A * T_STRIDE) * 4;
    cudaFuncSetAttribute(lin1_tiled,       cudaFuncAttributeMaxDynamicSharedMemorySize, SM_LIN1);
    cudaFuncSetAttribute(edge_gemm_kernel, cudaFuncAttributeMaxDynamicSharedMemorySize, SM_EDGE);
    cudaFuncSetAttribute(update_tiled,     cudaFuncAttributeMaxDynamicSharedMemorySize, SM_UPD);

    geom_kernel<<<(N_EDGES + 255) / 256, 256>>>(pos, edge_index);
    embed_kernel<<<(N_ATOMS * 32 + 255) / 256, 256>>>(atom_types, embedding);

    for (int b = 0; b < NB; b++) {
        lin1_tiled<<<N_ATILES, 256, SM_LIN1>>>(lin1_w + b * H * H);
        edge_gemm_kernel<<<148, 384, SM_EDGE>>>(filt_w1 + b * R * H, filt_b1 + b * H,
                                                filt_w2 + b * H * H, filt_b2 + b * H,
                                                edge_index);
        update_tiled<<<N_ATILES, 256, SM_UPD>>>(lin2_w + b * H * H, lin2_b + b * H,
                                                blk_w + b * H * H, blk_b + b * H);
    }

    zero_out_kernel<<<1, 64>>>(out);
    out_kernel<<<296, 256>>>(out_w1, out_b1, out_w2, out_b2, batch, out);
}

// round 6
// speedup vs baseline: 2.6233x; 1.2897x over previous
#include <cuda_runtime.h>
#include <math.h>
#include <stdint.h>

#define N_ATOMS 30000
#define N_EDGES 480000
#define H 128
#define R 50
#define NB 3
#define NEX 64
#define CUTOFF 10.0f
#define PI_F 3.14159265358979323846f

#define TILE_A 128
#define N_ATILES ((N_ATOMS + TILE_A - 1) / TILE_A)  // 235
#define T_STRIDE 132

// ---- edge mma kernel constants ----
#define ETILE 128
#define N_ETC (N_EDGES / ETILE)   // 3750
#define K1 56                     // stage-1 K padded (7 ksteps of 8)
#define ASTR1 60                  // A1 row stride (floats) — conflict-free frags
#define ASTR2 132                 // A2 row stride
#define BSTR 136                  // B row stride — (8k+n)%32 hits all banks
// smem float offsets
#define OFF_B1 0
#define OFF_B2 (OFF_B1 + K1 * BSTR)           // 7616
#define OFF_A1 (OFF_B2 + H * BSTR)            // 25024
#define OFF_A2 (OFF_A1 + ETILE * ASTR1)       // 32704
#define OFF_DS (OFF_A2 + ETILE * ASTR2)       // 49600
#define OFF_CS (OFF_DS + 128)
#define OFF_SS (OFF_CS + 128)
#define OFF_TS (OFF_SS + 128)
#define OFF_B1V (OFF_TS + 128)
#define OFF_B2V (OFF_B1V + 128)
#define SMF_TOTAL (OFF_B2V + 128)             // 50368 floats = 201472 B

typedef unsigned long long ull;

#define PACK2(d, x, y) asm("mov.b64 %0, {%1, %2};" : "=l"(d) : "f"(x), "f"(y))
#define UNPACK2(x, y, s) asm("mov.b64 {%0, %1}, %2;" : "=f"(x), "=f"(y) : "l"(s))
#define FMA2(d, a, b, c) asm("fma.rn.f32x2 %0, %1, %2, %3;" : "=l"(d) : "l"(a), "l"(b), "l"(c))
#define REDV4(p, a, b, c, d) \
    asm volatile("red.global.add.v4.f32 [%0], {%1,%2,%3,%4};" \
                 :: "l"(p), "f"(a), "f"(b), "f"(c), "f"(d) : "memory")
#define REDV2(p, a, b) \
    asm volatile("red.global.add.v2.f32 [%0], {%1,%2};" \
                 :: "l"(p), "f"(a), "f"(b) : "memory")
#define MMA_TF32(acc, a0, a1, a2, a3, b0, b1) \
    asm volatile("mma.sync.aligned.m16n8k8.row.col.f32.tf32.tf32.f32 " \
                 "{%0,%1,%2,%3},{%4,%5,%6,%7},{%8,%9},{%0,%1,%2,%3};" \
                 : "+f"((acc)[0]), "+f"((acc)[1]), "+f"((acc)[2]), "+f"((acc)[3]) \
                 : "r"(a0), "r"(a1), "r"(a2), "r"(a3), "r"(b0), "r"(b1))

__device__ __forceinline__ float tf32r(float x) {
    uint32_t u;
    asm("cvt.rna.tf32.f32 %0, %1;" : "=r"(u) : "f"(x));
    return __uint_as_float(u);
}
__device__ __forceinline__ float ftanh(float x) {
    float e = __expf(2.0f * x);
    return fmaf(-2.0f, __frcp_rn(e + 1.0f), 1.0f);
}
__device__ __forceinline__ uint32_t fbits(float x) { return __float_as_uint(x); }

// ---------------- device scratch (allocation-free) ----------------
__device__ float g_d[N_EDGES];
__device__ float g_C[N_EDGES];
__device__ float g_x[N_ATOMS * H];
__device__ float g_h[N_ATOMS * H];
__device__ float g_agg[N_ATOMS * H];

// ---------------- SIMT 8x8 register-tile GEMM (node kernels) ------------
template <int KDIM, int ASTRIDE>
__device__ __forceinline__ void gemm8x8(const float* __restrict__ At,
                                        const float* __restrict__ Bm,
                                        int rowbase, int colbase, ull acc[8][4]) {
    for (int k4 = 0; k4 < KDIM / 4; k4++) {
        float4 av[8];
#pragma unroll
        for (int i = 0; i < 8; i++)
            av[i] = *(const float4*)&At[(rowbase + i) * ASTRIDE + k4 * 4];
#pragma unroll
        for (int kk = 0; kk < 4; kk++) {
            int k = k4 * 4 + kk;
            float4 blo = *(const float4*)&Bm[k * H + colbase];
            float4 bhi = *(const float4*)&Bm[k * H + colbase + 4];
            ull bp[4];
            PACK2(bp[0], blo.x, blo.y); PACK2(bp[1], blo.z, blo.w);
            PACK2(bp[2], bhi.x, bhi.y); PACK2(bp[3], bhi.z, bhi.w);
#pragma unroll
            for (int i = 0; i < 8; i++) {
                float a = (kk == 0) ? av[i].x : (kk == 1) ? av[i].y
                          : (kk == 2) ? av[i].z : av[i].w;
                ull aa; PACK2(aa, a, a);
                FMA2(acc[i][0], aa, bp[0], acc[i][0]);
                FMA2(acc[i][1], aa, bp[1], acc[i][1]);
                FMA2(acc[i][2], aa, bp[2], acc[i][2]);
                FMA2(acc[i][3], aa, bp[3], acc[i][3]);
            }
        }
    }
}

__device__ __forceinline__ void init_acc(ull acc[8][4], const float* bias, int colbase) {
    ull b[4];
#pragma unroll
    for (int j = 0; j < 4; j++)
        PACK2(b[j], bias[colbase + 2 * j], bias[colbase + 2 * j + 1]);
#pragma unroll
    for (int i = 0; i < 8; i++)
#pragma unroll
        for (int j = 0; j < 4; j++) acc[i][j] = b[j];
}

__device__ __forceinline__ void init_acc_zero(ull acc[8][4]) {
#pragma unroll
    for (int i = 0; i < 8; i++)
#pragma unroll
        for (int j = 0; j < 4; j++) acc[i][j] = 0ull;
}

// ---------------- geometry: distances + cutoff only ----------------
__global__ void geom_kernel(const float* __restrict__ pos,
                            const int* __restrict__ ei) {
    int e = blockIdx.x * blockDim.x + threadIdx.x;
    if (e >= N_EDGES) return;
    int s = ei[e];
    int t = ei[N_EDGES + e];
    float dx = pos[3 * s + 0] - pos[3 * t + 0];
    float dy = pos[3 * s + 1] - pos[3 * t + 1];
    float dz = pos[3 * s + 2] - pos[3 * t + 2];
    float d = sqrtf(dx * dx + dy * dy + dz * dz + 1e-12f);
    g_d[e] = d;
    g_C[e] = (d < CUTOFF) ? 0.5f * (cosf(d * PI_F / CUTOFF) + 1.0f) : 0.0f;
}

// ---------------- embedding gather + zero agg ----------------
__global__ void embed_kernel(const int* __restrict__ types,
                             const float* __restrict__ emb) {
    int i = blockIdx.x * blockDim.x + threadIdx.x;
    if (i >= N_ATOMS * 32) return;
    int a = i >> 5;
    int c = i & 31;
    ((float4*)g_x)[a * 32 + c] = ((const float4*)emb)[types[a] * 32 + c];
    float4 z; z.x = z.y = z.z = z.w = 0.f;
    ((float4*)g_agg)[i] = z;
}

// ---------------- tiled lin1: h = x @ W (no bias) ----------------
__global__ __launch_bounds__(256) void lin1_tiled(const float* __restrict__ W) {
    extern __shared__ float sm[];
    float* Ws = sm;
    float* xb = Ws + H * H;
    int tid = threadIdx.x;
    for (int i = tid; i < H * H; i += 256) Ws[i] = W[i];
    __syncthreads();
    const int tx = tid & 15, ty = tid >> 4;
    const int colbase = tx * 8, rowbase = ty * 8;

    int a0 = blockIdx.x * TILE_A;
    for (int i = tid; i < TILE_A * 32; i += 256) {
        int row = i >> 5, c = i & 31;
        float4 v; v.x = v.y = v.z = v.w = 0.f;
        if (a0 + row < N_ATOMS) v = ((const float4*)g_x)[(a0 + row) * 32 + c];
        *(float4*)&xb[row * T_STRIDE + c * 4] = v;
    }
    __syncthreads();
    ull acc[8][4];
    init_acc_zero(acc);
    gemm8x8<H, T_STRIDE>(xb, Ws, rowbase, colbase, acc);
#pragma unroll
    for (int i = 0; i < 8; i++) {
        int a = a0 + rowbase + i;
        if (a < N_ATOMS) {
            float v[8];
#pragma unroll
            for (int j = 0; j < 4; j++) UNPACK2(v[2 * j], v[2 * j + 1], acc[i][j]);
            float4 o0; o0.x = v[0]; o0.y = v[1]; o0.z = v[2]; o0.w = v[3];
            float4 o1; o1.x = v[4]; o1.y = v[5]; o1.z = v[6]; o1.w = v[7];
            *(float4*)&g_h[a * H + colbase] = o0;
            *(float4*)&g_h[a * H + colbase + 4] = o1;
        }
    }
}

// ======== edge kernel: rbf + filter net via mma.sync tf32 + scatter ========
// 256 threads = 8 warps. Warp (wr=wid&3, wc=wid>>2): 32 edges x 64 cols,
// 2 m-tiles (16) x 8 n-tiles (8). mma.sync m16n8k8 tf32.
__global__ __launch_bounds__(256) void edge_mma_kernel(
        const float* __restrict__ W1, const float* __restrict__ b1,
        const float* __restrict__ W2, const float* __restrict__ b2,
        const int* __restrict__ ei) {
    extern __shared__ float sm[];
    float* B1s = sm + OFF_B1;
    float* B2s = sm + OFF_B2;
    float* A1  = sm + OFF_A1;
    float* A2  = sm + OFF_A2;
    float* ds  = sm + OFF_DS;
    float* cs  = sm + OFF_CS;
    int*   ss  = (int*)(sm + OFF_SS);
    int*   ts  = (int*)(sm + OFF_TS);
    float* b1s = sm + OFF_B1V;
    float* b2s = sm + OFF_B2V;

    const int tid = threadIdx.x;
    const int wid = tid >> 5, lane = tid & 31;
    const int g = lane >> 2, t = lane & 3;
    const int mb = (wid & 3) * 32;
    const int nb = (wid >> 2) * 64;

    // weights into smem, rounded to tf32 once
    for (int i = tid; i < K1 * H; i += 256) {
        int k = i >> 7, n = i & 127;
        B1s[k * BSTR + n] = (k < R) ? tf32r(W1[k * H + n]) : 0.0f;
    }
    for (int i = tid; i < H * H; i += 256) {
        int k = i >> 7, n = i & 127;
        B2s[k * BSTR + n] = tf32r(W2[k * H + n]);
    }
    if (tid < 128) { b1s[tid] = b1[tid]; b2s[tid] = b2[tid]; }
    __syncthreads();

    const float delta = CUTOFF / (float)(R - 1);
    const float coeff = -0.5f / (delta * delta);

    for (int tile = blockIdx.x; tile < N_ETC; tile += gridDim.x) {
        int e0 = tile * ETILE;
        if (tid < 128) {
            ds[tid] = g_d[e0 + tid];
            cs[tid] = g_C[e0 + tid];
            ss[tid] = ei[e0 + tid];
            ts[tid] = ei[N_EDGES + e0 + tid];
        }
        __syncthreads();

        // rbf tile -> A1 (tf32-rounded), 2 threads per edge row
        {
            int e = tid >> 1;
            int k0 = (tid & 1) * 28;
            float dv = ds[e];
#pragma unroll
            for (int k = k0; k < k0 + 28; k++) {
                float v = 0.0f;
                if (k < R) { float u = dv - (float)k * delta; v = tf32r(__expf(coeff * u * u)); }
                A1[e * ASTR1 + k] = v;
            }
        }
        __syncthreads();

        float acc[2][8][4];
        // ---- stage 1: D1 = rbf @ W1 + b1 ----
#pragma unroll
        for (int mt = 0; mt < 2; mt++)
#pragma unroll
            for (int j = 0; j < 8; j++) {
                int c0 = nb + j * 8 + 2 * t;
                acc[mt][j][0] = b1s[c0]; acc[mt][j][1] = b1s[c0 + 1];
                acc[mt][j][2] = b1s[c0]; acc[mt][j][3] = b1s[c0 + 1];
            }
#pragma unroll
        for (int ks = 0; ks < K1 / 8; ks++) {
            int kb = ks * 8;
            uint32_t af[2][4];
#pragma unroll
            for (int mt = 0; mt < 2; mt++) {
                int r = mb + mt * 16;
                af[mt][0] = fbits(A1[(r + g) * ASTR1 + kb + t]);
                af[mt][1] = fbits(A1[(r + g + 8) * ASTR1 + kb + t]);
                af[mt][2] = fbits(A1[(r + g) * ASTR1 + kb + t + 4]);
                af[mt][3] = fbits(A1[(r + g + 8) * ASTR1 + kb + t + 4]);
            }
#pragma unroll
            for (int j = 0; j < 8; j++) {
                int n0 = nb + j * 8;
                uint32_t bf0 = fbits(B1s[(kb + t) * BSTR + n0 + g]);
                uint32_t bf1 = fbits(B1s[(kb + t + 4) * BSTR + n0 + g]);
                MMA_TF32(acc[0][j], af[0][0], af[0][1], af[0][2], af[0][3], bf0, bf1);
                MMA_TF32(acc[1][j], af[1][0], af[1][1], af[1][2], af[1][3], bf0, bf1);
            }
        }
        // tanh -> A2 (tf32-rounded)
#pragma unroll
        for (int mt = 0; mt < 2; mt++) {
            int r = mb + mt * 16;
#pragma unroll
            for (int j = 0; j < 8; j++) {
                int c0 = nb + j * 8 + 2 * t;
                float2 lo, hi;
                lo.x = tf32r(ftanh(acc[mt][j][0])); lo.y = tf32r(ftanh(acc[mt][j][1]));
                hi.x = tf32r(ftanh(acc[mt][j][2])); hi.y = tf32r(ftanh(acc[mt][j][3]));
                *(float2*)&A2[(r + g) * ASTR2 + c0] = lo;
                *(float2*)&A2[(r + g + 8) * ASTR2 + c0] = hi;
            }
        }
        __syncthreads();

        // ---- stage 2: D2 = t @ W2 + b2 ----
#pragma unroll
        for (int mt = 0; mt < 2; mt++)
#pragma unroll
            for (int j = 0; j < 8; j++) {
                int c0 = nb + j * 8 + 2 * t;
                acc[mt][j][0] = b2s[c0]; acc[mt][j][1] = b2s[c0 + 1];
                acc[mt][j][2] = b2s[c0]; acc[mt][j][3] = b2s[c0 + 1];
            }
#pragma unroll
        for (int ks = 0; ks < H / 8; ks++) {
            int kb = ks * 8;
            uint32_t af[2][4];
#pragma unroll
            for (int mt = 0; mt < 2; mt++) {
                int r = mb + mt * 16;
                af[mt][0] = fbits(A2[(r + g) * ASTR2 + kb + t]);
                af[mt][1] = fbits(A2[(r + g + 8) * ASTR2 + kb + t]);
                af[mt][2] = fbits(A2[(r + g) * ASTR2 + kb + t + 4]);
                af[mt][3] = fbits(A2[(r + g + 8) * ASTR2 + kb + t + 4]);
            }
#pragma unroll
            for (int j = 0; j < 8; j++) {
                int n0 = nb + j * 8;
                uint32_t bf0 = fbits(B2s[(kb + t) * BSTR + n0 + g]);
                uint32_t bf1 = fbits(B2s[(kb + t + 4) * BSTR + n0 + g]);
                MMA_TF32(acc[0][j], af[0][0], af[0][1], af[0][2], af[0][3], bf0, bf1);
                MMA_TF32(acc[1][j], af[1][0], af[1][1], af[1][2], af[1][3], bf0, bf1);
            }
        }

        // ---- epilogue: msg = D2 * C * h[src] -> red.v2 to agg[dst] ----
#pragma unroll
        for (int mt = 0; mt < 2; mt++) {
#pragma unroll
            for (int half = 0; half < 2; half++) {
                int row = mb + mt * 16 + g + half * 8;
                float c = cs[row];
                if (c != 0.0f) {
                    const float* hp = g_h + (size_t)ss[row] * H + nb;
                    float* ap = g_agg + (size_t)ts[row] * H + nb;
#pragma unroll
                    for (int j = 0; j < 8; j++) {
                        int o = j * 8 + 2 * t;
                        float2 h2 = *(const float2*)(hp + o);
                        float v0 = acc[mt][j][half * 2 + 0] * c * h2.x;
                        float v1 = acc[mt][j][half * 2 + 1] * c * h2.y;
                        REDV2(ap + o, v0, v1);
                    }
                }
            }
        }
        __syncthreads();
    }
}

// ------- tiled node update: x += tanh(agg@lin2+b1) @ blk + b2; rezero agg ---
__global__ __launch_bounds__(256) void update_tiled(
        const float* __restrict__ lin2_w, const float* __restrict__ lin2_b,
        const float* __restrict__ blk_w, const float* __restrict__ blk_b) {
    extern __shared__ float sm[];
    float* As = sm;
    float* Bs = As + H * H;
    float* b1s = Bs + H * H;
    float* b2s = b1s + H;
    float* buf = b2s + H;
    int tid = threadIdx.x;
    for (int i = tid; i < H * H; i += 256) { As[i] = lin2_w[i]; Bs[i] = blk_w[i]; }
    if (tid < H) { b1s[tid] = lin2_b[tid]; b2s[tid] = blk_b[tid]; }
    __syncthreads();

    const int tx = tid & 15, ty = tid >> 4;
    const int colbase = tx * 8, rowbase = ty * 8;

    int a0 = blockIdx.x * TILE_A;
    for (int i = tid; i < TILE_A * 32; i += 256) {
        int row = i >> 5, c = i & 31;
        float4 v; v.x = v.y = v.z = v.w = 0.f;
        if (a0 + row < N_ATOMS) {
            v = ((const float4*)g_agg)[(a0 + row) * 32 + c];
            float4 z; z.x = z.y = z.z = z.w = 0.f;
            ((float4*)g_agg)[(a0 + row) * 32 + c] = z;
        }
        *(float4*)&buf[row * T_STRIDE + c * 4] = v;
    }
    __syncthreads();

    ull acc[8][4];
    init_acc(acc, b1s, colbase);
    gemm8x8<H, T_STRIDE>(buf, As, rowbase, colbase, acc);
    __syncthreads();
#pragma unroll
    for (int i = 0; i < 8; i++) {
        float v[8];
#pragma unroll
        for (int j = 0; j < 4; j++) UNPACK2(v[2 * j], v[2 * j + 1], acc[i][j]);
#pragma unroll
        for (int j = 0; j < 8; j++) v[j] = tanhf(v[j]);
        float4 o0; o0.x = v[0]; o0.y = v[1]; o0.z = v[2]; o0.w = v[3];
        float4 o1; o1.x = v[4]; o1.y = v[5]; o1.z = v[6]; o1.w = v[7];
        *(float4*)&buf[(rowbase + i) * T_STRIDE + colbase] = o0;
        *(float4*)&buf[(rowbase + i) * T_STRIDE + colbase + 4] = o1;
    }
    __syncthreads();

    init_acc(acc, b2s, colbase);
    gemm8x8<H, T_STRIDE>(buf, Bs, rowbase, colbase, acc);

#pragma unroll
    for (int i = 0; i < 8; i++) {
        int a = a0 + rowbase + i;
        if (a < N_ATOMS) {
            float v[8];
#pragma unroll
            for (int j = 0; j < 4; j++) UNPACK2(v[2 * j], v[2 * j + 1], acc[i][j]);
            float4 x0 = *(const float4*)&g_x[a * H + colbase];
            float4 x1 = *(const float4*)&g_x[a * H + colbase + 4];
            x0.x += v[0]; x0.y += v[1]; x0.z += v[2]; x0.w += v[3];
            x1.x += v[4]; x1.y += v[5]; x1.z += v[6]; x1.w += v[7];
            *(float4*)&g_x[a * H + colbase] = x0;
            *(float4*)&g_x[a * H + colbase + 4] = x1;
        }
    }
}

// ---------------- output head + per-molecule reduction ----------------
__global__ void zero_out_kernel(float* out) {
    if (threadIdx.x < NEX) out[threadIdx.x] = 0.0f;
}

__global__ void out_kernel(const float* __restrict__ w1, const float* __restrict__ b1v,
                           const float* __restrict__ w2, const float* __restrict__ b2v,
                           const int* __restrict__ batch, float* __restrict__ out) {
    __shared__ float w1s[H * 64];
    __shared__ float w2s[64];
    __shared__ float b1s[64];
    __shared__ float xb[8 * H];
    for (int i = threadIdx.x; i < H * 64; i += blockDim.x) w1s[i] = w1[i];
    if (threadIdx.x < 64) { w2s[threadIdx.x] = w2[threadIdx.x]; b1s[threadIdx.x] = b1v[threadIdx.x]; }
    __syncthreads();
    float ob2 = b2v[0];
    int lane = threadIdx.x & 31;
    int w = threadIdx.x >> 5;
    int wpb = blockDim.x >> 5;
    float* rb = xb + w * H;
    for (int a = blockIdx.x * wpb + w; a < N_ATOMS; a += gridDim.x * wpb) {
        float4 xv = ((const float4*)g_x)[a * 32 + lane];
        ((float4*)rb)[lane] = xv;
        __syncwarp();
        float a0 = b1s[lane], a1 = b1s[lane + 32];
#pragma unroll 4
        for (int k = 0; k < H; k++) {
            float xk = rb[k];
            a0 = fmaf(xk, w1s[k * 64 + lane], a0);
            a1 = fmaf(xk, w1s[k * 64 + lane + 32], a1);
        }
        __syncwarp();
        float part = tanhf(a0) * w2s[lane] + tanhf(a1) * w2s[lane + 32];
#pragma unroll
        for (int off = 16; off; off >>= 1)
            part += __shfl_down_sync(0xffffffffu, part, off);
        if (lane == 0) atomicAdd(&out[batch[a]], part + ob2);
    }
}

// ---------------- host launcher ----------------
extern "C" void kernel_launch(void* const* d_in, const int* in_sizes, int n_in,
                              void* d_out, int out_size) {
    const float* pos        = (const float*)d_in[0];
    const int*   atom_types = (const int*)  d_in[1];
    const int*   edge_index = (const int*)  d_in[2];
    const int*   batch      = (const int*)  d_in[3];
    const float* embedding  = (const float*)d_in[4];
    const float* filt_w1    = (const float*)d_in[5];
    const float* filt_b1    = (const float*)d_in[6];
    const float* filt_w2    = (const float*)d_in[7];
    const float* filt_b2    = (const float*)d_in[8];
    const float* lin1_w     = (const float*)d_in[9];
    const float* lin2_w     = (const float*)d_in[10];
    const float* lin2_b     = (const float*)d_in[11];
    const float* blk_w      = (const float*)d_in[12];
    const float* blk_b      = (const float*)d_in[13];
    const float* out_w1     = (const float*)d_in[14];
    const float* out_b1     = (const float*)d_in[15];
    const float* out_w2     = (const float*)d_in[16];
    const float* out_b2     = (const float*)d_in[17];
    float* out = (float*)d_out;

    const int SM_LIN1 = (H * H + TILE_A * T_STRIDE) * 4;
    const int SM_EDGE = SMF_TOTAL * 4;   // 201472 bytes
    const int SM_UPD  = (2 * H * H + 2 * H + TILE_A * T_STRIDE) * 4;
    cudaFuncSetAttribute(lin1_tiled,      cudaFuncAttributeMaxDynamicSharedMemorySize, SM_LIN1);
    cudaFuncSetAttribute(edge_mma_kernel, cudaFuncAttributeMaxDynamicSharedMemorySize, SM_EDGE);
    cudaFuncSetAttribute(update_tiled,    cudaFuncAttributeMaxDynamicSharedMemorySize, SM_UPD);

    geom_kernel<<<(N_EDGES + 255) / 256, 256>>>(pos, edge_index);
    embed_kernel<<<(N_ATOMS * 32 + 255) / 256, 256>>>(atom_types, embedding);

    for (int b = 0; b < NB; b++) {
        lin1_tiled<<<N_ATILES, 256, SM_LIN1>>>(lin1_w + b * H * H);
        edge_mma_kernel<<<148, 256, SM_EDGE>>>(filt_w1 + b * R * H, filt_b1 + b * H,
                                               filt_w2 + b * H * H, filt_b2 + b * H,
                                               edge_index);
        update_tiled<<<N_ATILES, 256, SM_UPD>>>(lin2_w + b * H * H, lin2_b + b * H,
                                                blk_w + b * H * H, blk_b + b * H);
    }

    zero_out_kernel<<<1, 64>>>(out);
    out_kernel<<<296, 256>>>(out_w1, out_b1, out_w2, out_b2, batch, out);
}

// round 7
// speedup vs baseline: 3.3658x; 1.2830x over previous
#include <cuda_runtime.h>
#include <math.h>
#include <stdint.h>

#define N_ATOMS 30000
#define N_EDGES 480000
#define H 128
#define R 50
#define NB 3
#define NEX 64
#define CUTOFF 10.0f
#define PI_F 3.14159265358979323846f

#define TILE_A 128
#define N_ATILES ((N_ATOMS + TILE_A - 1) / TILE_A)  // 235
#define T_STRIDE 132

// ---- edge mma kernel constants ----
#define ETILE 128
#define N_ETC (N_EDGES / ETILE)   // 3750
#define K1 56                     // stage-1 K padded (7 ksteps of 8)
#define NKS1 7
#define NKS2 16
#define ASTR1 60                  // A1 row stride (floats) — conflict-free frags
#define ASTR2 132                 // A2 row stride
// smem float offsets
#define OFF_B1P 0                               // 7*128*4 float2 = 7168 floats
#define OFF_B2P (OFF_B1P + NKS1 * 128 * 8)      // 7168
#define OFF_A1  (OFF_B2P + NKS2 * 128 * 8)      // 23552
#define OFF_A2  (OFF_A1 + ETILE * ASTR1)        // 31232
#define OFF_CS  (OFF_A2 + ETILE * ASTR2)        // 48128
#define OFF_SS  (OFF_CS + 128)
#define OFF_TS  (OFF_SS + 128)
#define OFF_B1V (OFF_TS + 128)
#define OFF_B2V (OFF_B1V + 128)
#define SMF_TOTAL (OFF_B2V + 128)               // 48768 floats = 195072 B

typedef unsigned long long ull;

#define PACK2(d, x, y) asm("mov.b64 %0, {%1, %2};" : "=l"(d) : "f"(x), "f"(y))
#define UNPACK2(x, y, s) asm("mov.b64 {%0, %1}, %2;" : "=f"(x), "=f"(y) : "l"(s))
#define FMA2(d, a, b, c) asm("fma.rn.f32x2 %0, %1, %2, %3;" : "=l"(d) : "l"(a), "l"(b), "l"(c))
#define REDV2(p, a, b) \
    asm volatile("red.global.add.v2.f32 [%0], {%1,%2};" \
                 :: "l"(p), "f"(a), "f"(b) : "memory")
#define MMA_TF32(acc, a0, a1, a2, a3, b0, b1) \
    asm volatile("mma.sync.aligned.m16n8k8.row.col.f32.tf32.tf32.f32 " \
                 "{%0,%1,%2,%3},{%4,%5,%6,%7},{%8,%9},{%0,%1,%2,%3};" \
                 : "+f"((acc)[0]), "+f"((acc)[1]), "+f"((acc)[2]), "+f"((acc)[3]) \
                 : "r"(a0), "r"(a1), "r"(a2), "r"(a3), "r"(b0), "r"(b1))

__device__ __forceinline__ float tf32r(float x) {
    uint32_t u;
    asm("cvt.rna.tf32.f32 %0, %1;" : "=r"(u) : "f"(x));
    return __uint_as_float(u);
}
__device__ __forceinline__ float ftanh(float x) {
    float e = __expf(2.0f * x);
    return fmaf(-2.0f, __frcp_rn(e + 1.0f), 1.0f);
}
__device__ __forceinline__ uint32_t fbits(float x) { return __float_as_uint(x); }

// ---------------- device scratch (allocation-free) ----------------
__device__ float g_d[N_EDGES];
__device__ float g_C[N_EDGES];
__device__ float g_x[N_ATOMS * H];
__device__ float g_h[N_ATOMS * H];
__device__ float g_agg[N_ATOMS * H];

// ---------------- SIMT 8x8 register-tile GEMM (node kernels) ------------
template <int KDIM, int ASTRIDE>
__device__ __forceinline__ void gemm8x8(const float* __restrict__ At,
                                        const float* __restrict__ Bm,
                                        int rowbase, int colbase, ull acc[8][4]) {
    for (int k4 = 0; k4 < KDIM / 4; k4++) {
        float4 av[8];
#pragma unroll
        for (int i = 0; i < 8; i++)
            av[i] = *(const float4*)&At[(rowbase + i) * ASTRIDE + k4 * 4];
#pragma unroll
        for (int kk = 0; kk < 4; kk++) {
            int k = k4 * 4 + kk;
            float4 blo = *(const float4*)&Bm[k * H + colbase];
            float4 bhi = *(const float4*)&Bm[k * H + colbase + 4];
            ull bp[4];
            PACK2(bp[0], blo.x, blo.y); PACK2(bp[1], blo.z, blo.w);
            PACK2(bp[2], bhi.x, bhi.y); PACK2(bp[3], bhi.z, bhi.w);
#pragma unroll
            for (int i = 0; i < 8; i++) {
                float a = (kk == 0) ? av[i].x : (kk == 1) ? av[i].y
                          : (kk == 2) ? av[i].z : av[i].w;
                ull aa; PACK2(aa, a, a);
                FMA2(acc[i][0], aa, bp[0], acc[i][0]);
                FMA2(acc[i][1], aa, bp[1], acc[i][1]);
                FMA2(acc[i][2], aa, bp[2], acc[i][2]);
                FMA2(acc[i][3], aa, bp[3], acc[i][3]);
            }
        }
    }
}

__device__ __forceinline__ void init_acc(ull acc[8][4], const float* bias, int colbase) {
    ull b[4];
#pragma unroll
    for (int j = 0; j < 4; j++)
        PACK2(b[j], bias[colbase + 2 * j], bias[colbase + 2 * j + 1]);
#pragma unroll
    for (int i = 0; i < 8; i++)
#pragma unroll
        for (int j = 0; j < 4; j++) acc[i][j] = b[j];
}

__device__ __forceinline__ void init_acc_zero(ull acc[8][4]) {
#pragma unroll
    for (int i = 0; i < 8; i++)
#pragma unroll
        for (int j = 0; j < 4; j++) acc[i][j] = 0ull;
}

// ---------------- geometry: distances + cutoff only ----------------
__global__ void geom_kernel(const float* __restrict__ pos,
                            const int* __restrict__ ei) {
    int e = blockIdx.x * blockDim.x + threadIdx.x;
    if (e >= N_EDGES) return;
    int s = ei[e];
    int t = ei[N_EDGES + e];
    float dx = pos[3 * s + 0] - pos[3 * t + 0];
    float dy = pos[3 * s + 1] - pos[3 * t + 1];
    float dz = pos[3 * s + 2] - pos[3 * t + 2];
    float d = sqrtf(dx * dx + dy * dy + dz * dz + 1e-12f);
    g_d[e] = d;
    g_C[e] = (d < CUTOFF) ? 0.5f * (cosf(d * PI_F / CUTOFF) + 1.0f) : 0.0f;
}

// ---------------- embedding gather + zero agg ----------------
__global__ void embed_kernel(const int* __restrict__ types,
                             const float* __restrict__ emb) {
    int i = blockIdx.x * blockDim.x + threadIdx.x;
    if (i >= N_ATOMS * 32) return;
    int a = i >> 5;
    int c = i & 31;
    ((float4*)g_x)[a * 32 + c] = ((const float4*)emb)[types[a] * 32 + c];
    float4 z; z.x = z.y = z.z = z.w = 0.f;
    ((float4*)g_agg)[i] = z;
}

// ---------------- tiled lin1: h = x @ W (no bias) ----------------
__global__ __launch_bounds__(256) void lin1_tiled(const float* __restrict__ W) {
    extern __shared__ float sm[];
    float* Ws = sm;
    float* xb = Ws + H * H;
    int tid = threadIdx.x;
    for (int i = tid; i < H * H; i += 256) Ws[i] = W[i];
    __syncthreads();
    const int tx = tid & 15, ty = tid >> 4;
    const int colbase = tx * 8, rowbase = ty * 8;

    int a0 = blockIdx.x * TILE_A;
    for (int i = tid; i < TILE_A * 32; i += 256) {
        int row = i >> 5, c = i & 31;
        float4 v; v.x = v.y = v.z = v.w = 0.f;
        if (a0 + row < N_ATOMS) v = ((const float4*)g_x)[(a0 + row) * 32 + c];
        *(float4*)&xb[row * T_STRIDE + c * 4] = v;
    }
    __syncthreads();
    ull acc[8][4];
    init_acc_zero(acc);
    gemm8x8<H, T_STRIDE>(xb, Ws, rowbase, colbase, acc);
#pragma unroll
    for (int i = 0; i < 8; i++) {
        int a = a0 + rowbase + i;
        if (a < N_ATOMS) {
            float v[8];
#pragma unroll
            for (int j = 0; j < 4; j++) UNPACK2(v[2 * j], v[2 * j + 1], acc[i][j]);
            float4 o0; o0.x = v[0]; o0.y = v[1]; o0.z = v[2]; o0.w = v[3];
            float4 o1; o1.x = v[4]; o1.y = v[5]; o1.z = v[6]; o1.w = v[7];
            *(float4*)&g_h[a * H + colbase] = o0;
            *(float4*)&g_h[a * H + colbase + 4] = o1;
        }
    }
}

// ======== edge kernel: rbf + filter net via mma.sync tf32 + scatter ========
// 512 threads = 16 warps in a 4x4 grid: warp (wr=wid&3, wc=wid>>2) handles
// 32 edges x 32 cols as 2 m16-tiles x 4 n8-tiles. B is pair-interleaved
// float2 so each B fragment is a single LDS.64.
__global__ __launch_bounds__(512) void edge_mma_kernel(
        const float* __restrict__ W1, const float* __restrict__ b1,
        const float* __restrict__ W2, const float* __restrict__ b2,
        const int* __restrict__ ei) {
    extern __shared__ float sm[];
    float2* B1p = (float2*)(sm + OFF_B1P);
    float2* B2p = (float2*)(sm + OFF_B2P);
    float* A1  = sm + OFF_A1;
    float* A2  = sm + OFF_A2;
    float* cs  = sm + OFF_CS;
    int*   ss  = (int*)(sm + OFF_SS);
    int*   ts  = (int*)(sm + OFF_TS);
    float* b1s = sm + OFF_B1V;
    float* b2s = sm + OFF_B2V;

    const int tid = threadIdx.x;
    const int wid = tid >> 5, lane = tid & 31;
    const int g = lane >> 2, t = lane & 3;
    const int mb = (wid & 3) * 32;
    const int nb = (wid >> 2) * 32;

    // weights into pair-interleaved smem, rounded to tf32 once
    for (int i = tid; i < NKS1 * 128 * 4; i += 512) {
        int t4 = i & 3, n = (i >> 2) & 127, ks = i >> 9;
        int k0 = 8 * ks + t4;
        float2 v;
        v.x = (k0 < R) ? tf32r(W1[k0 * H + n]) : 0.0f;
        v.y = (k0 + 4 < R) ? tf32r(W1[(k0 + 4) * H + n]) : 0.0f;
        B1p[i] = v;
    }
    for (int i = tid; i < NKS2 * 128 * 4; i += 512) {
        int t4 = i & 3, n = (i >> 2) & 127, ks = i >> 9;
        int k0 = 8 * ks + t4;
        float2 v;
        v.x = tf32r(W2[k0 * H + n]);
        v.y = tf32r(W2[(k0 + 4) * H + n]);
        B2p[i] = v;
    }
    if (tid < 128) { b1s[tid] = b1[tid]; b2s[tid] = b2[tid]; }
    __syncthreads();

    const float delta = CUTOFF / (float)(R - 1);
    const float coeff = -0.5f / (delta * delta);

    for (int tile = blockIdx.x; tile < N_ETC; tile += gridDim.x) {
        int e0 = tile * ETILE;
        if (tid < 128) {
            cs[tid] = g_C[e0 + tid];
            ss[tid] = ei[e0 + tid];
            ts[tid] = ei[N_EDGES + e0 + tid];
        }
        // rbf tile -> A1 (tf32-rounded); 4 threads per edge, 14 cols each
        {
            int e = tid >> 2;
            int k0 = (tid & 3) * 14;
            float dv = g_d[e0 + e];
#pragma unroll
            for (int k = k0; k < k0 + 14; k++) {
                float v = 0.0f;
                if (k < R) { float u = dv - (float)k * delta; v = tf32r(__expf(coeff * u * u)); }
                A1[e * ASTR1 + k] = v;
            }
        }
        __syncthreads();

        float acc[2][4][4];
        // ---- stage 1: D1 = rbf @ W1 + b1 ----
#pragma unroll
        for (int mt = 0; mt < 2; mt++)
#pragma unroll
            for (int j = 0; j < 4; j++) {
                int c0 = nb + j * 8 + 2 * t;
                acc[mt][j][0] = b1s[c0]; acc[mt][j][1] = b1s[c0 + 1];
                acc[mt][j][2] = b1s[c0]; acc[mt][j][3] = b1s[c0 + 1];
            }
#pragma unroll
        for (int ks = 0; ks < NKS1; ks++) {
            int kb = ks * 8;
            uint32_t af[2][4];
#pragma unroll
            for (int mt = 0; mt < 2; mt++) {
                const float* ar = A1 + (mb + mt * 16 + g) * ASTR1 + kb;
                af[mt][0] = fbits(ar[t]);
                af[mt][1] = fbits(ar[8 * ASTR1 + t]);
                af[mt][2] = fbits(ar[t + 4]);
                af[mt][3] = fbits(ar[8 * ASTR1 + t + 4]);
            }
#pragma unroll
            for (int j = 0; j < 4; j++) {
                float2 bp = B1p[(ks * 128 + nb + j * 8 + g) * 4 + t];
                uint32_t bf0 = fbits(bp.x), bf1 = fbits(bp.y);
                MMA_TF32(acc[0][j], af[0][0], af[0][1], af[0][2], af[0][3], bf0, bf1);
                MMA_TF32(acc[1][j], af[1][0], af[1][1], af[1][2], af[1][3], bf0, bf1);
            }
        }
        // tanh -> A2 (tf32-rounded)
#pragma unroll
        for (int mt = 0; mt < 2; mt++) {
            int r = mb + mt * 16;
#pragma unroll
            for (int j = 0; j < 4; j++) {
                int c0 = nb + j * 8 + 2 * t;
                float2 lo, hi;
                lo.x = tf32r(ftanh(acc[mt][j][0])); lo.y = tf32r(ftanh(acc[mt][j][1]));
                hi.x = tf32r(ftanh(acc[mt][j][2])); hi.y = tf32r(ftanh(acc[mt][j][3]));
                *(float2*)&A2[(r + g) * ASTR2 + c0] = lo;
                *(float2*)&A2[(r + g + 8) * ASTR2 + c0] = hi;
            }
        }
        __syncthreads();

        // ---- stage 2: D2 = t @ W2 + b2 ----
#pragma unroll
        for (int mt = 0; mt < 2; mt++)
#pragma unroll
            for (int j = 0; j < 4; j++) {
                int c0 = nb + j * 8 + 2 * t;
                acc[mt][j][0] = b2s[c0]; acc[mt][j][1] = b2s[c0 + 1];
                acc[mt][j][2] = b2s[c0]; acc[mt][j][3] = b2s[c0 + 1];
            }
#pragma unroll 4
        for (int ks = 0; ks < NKS2; ks++) {
            int kb = ks * 8;
            uint32_t af[2][4];
#pragma unroll
            for (int mt = 0; mt < 2; mt++) {
                const float* ar = A2 + (mb + mt * 16 + g) * ASTR2 + kb;
                af[mt][0] = fbits(ar[t]);
                af[mt][1] = fbits(ar[8 * ASTR2 + t]);
                af[mt][2] = fbits(ar[t + 4]);
                af[mt][3] = fbits(ar[8 * ASTR2 + t + 4]);
            }
#pragma unroll
            for (int j = 0; j < 4; j++) {
                float2 bp = B2p[(ks * 128 + nb + j * 8 + g) * 4 + t];
                uint32_t bf0 = fbits(bp.x), bf1 = fbits(bp.y);
                MMA_TF32(acc[0][j], af[0][0], af[0][1], af[0][2], af[0][3], bf0, bf1);
                MMA_TF32(acc[1][j], af[1][0], af[1][1], af[1][2], af[1][3], bf0, bf1);
            }
        }

        // ---- epilogue: msg = D2 * C * h[src] -> red.v2 to agg[dst] ----
#pragma unroll
        for (int mt = 0; mt < 2; mt++) {
#pragma unroll
            for (int half = 0; half < 2; half++) {
                int row = mb + mt * 16 + half * 8 + g;
                float c = cs[row];
                if (c != 0.0f) {
                    const float* hp = g_h + (size_t)ss[row] * H + nb;
                    float* ap = g_agg + (size_t)ts[row] * H + nb;
#pragma unroll
                    for (int j = 0; j < 4; j++) {
                        int o = j * 8 + 2 * t;
                        float2 h2 = *(const float2*)(hp + o);
                        float v0 = acc[mt][j][half * 2 + 0] * c * h2.x;
                        float v1 = acc[mt][j][half * 2 + 1] * c * h2.y;
                        REDV2(ap + o, v0, v1);
                    }
                }
            }
        }
        __syncthreads();
    }
}

// ------- tiled node update: x += tanh(agg@lin2+b1) @ blk + b2; rezero agg ---
__global__ __launch_bounds__(256) void update_tiled(
        const float* __restrict__ lin2_w, const float* __restrict__ lin2_b,
        const float* __restrict__ blk_w, const float* __restrict__ blk_b) {
    extern __shared__ float sm[];
    float* As = sm;
    float* Bs = As + H * H;
    float* b1s = Bs + H * H;
    float* b2s = b1s + H;
    float* buf = b2s + H;
    int tid = threadIdx.x;
    for (int i = tid; i < H * H; i += 256) { As[i] = lin2_w[i]; Bs[i] = blk_w[i]; }
    if (tid < H) { b1s[tid] = lin2_b[tid]; b2s[tid] = blk_b[tid]; }
    __syncthreads();

    const int tx = tid & 15, ty = tid >> 4;
    const int colbase = tx * 8, rowbase = ty * 8;

    int a0 = blockIdx.x * TILE_A;
    for (int i = tid; i < TILE_A * 32; i += 256) {
        int row = i >> 5, c = i & 31;
        float4 v; v.x = v.y = v.z = v.w = 0.f;
        if (a0 + row < N_ATOMS) {
            v = ((const float4*)g_agg)[(a0 + row) * 32 + c];
            float4 z; z.x = z.y = z.z = z.w = 0.f;
            ((float4*)g_agg)[(a0 + row) * 32 + c] = z;
        }
        *(float4*)&buf[row * T_STRIDE + c * 4] = v;
    }
    __syncthreads();

    ull acc[8][4];
    init_acc(acc, b1s, colbase);
    gemm8x8<H, T_STRIDE>(buf, As, rowbase, colbase, acc);
    __syncthreads();
#pragma unroll
    for (int i = 0; i < 8; i++) {
        float v[8];
#pragma unroll
        for (int j = 0; j < 4; j++) UNPACK2(v[2 * j], v[2 * j + 1], acc[i][j]);
#pragma unroll
        for (int j = 0; j < 8; j++) v[j] = tanhf(v[j]);
        float4 o0; o0.x = v[0]; o0.y = v[1]; o0.z = v[2]; o0.w = v[3];
        float4 o1; o1.x = v[4]; o1.y = v[5]; o1.z = v[6]; o1.w = v[7];
        *(float4*)&buf[(rowbase + i) * T_STRIDE + colbase] = o0;
        *(float4*)&buf[(rowbase + i) * T_STRIDE + colbase + 4] = o1;
    }
    __syncthreads();

    init_acc(acc, b2s, colbase);
    gemm8x8<H, T_STRIDE>(buf, Bs, rowbase, colbase, acc);

#pragma unroll
    for (int i = 0; i < 8; i++) {
        int a = a0 + rowbase + i;
        if (a < N_ATOMS) {
            float v[8];
#pragma unroll
            for (int j = 0; j < 4; j++) UNPACK2(v[2 * j], v[2 * j + 1], acc[i][j]);
            float4 x0 = *(const float4*)&g_x[a * H + colbase];
            float4 x1 = *(const float4*)&g_x[a * H + colbase + 4];
            x0.x += v[0]; x0.y += v[1]; x0.z += v[2]; x0.w += v[3];
            x1.x += v[4]; x1.y += v[5]; x1.z += v[6]; x1.w += v[7];
            *(float4*)&g_x[a * H + colbase] = x0;
            *(float4*)&g_x[a * H + colbase + 4] = x1;
        }
    }
}

// ---------------- output head + per-molecule reduction ----------------
__global__ void zero_out_kernel(float* out) {
    if (threadIdx.x < NEX) out[threadIdx.x] = 0.0f;
}

__global__ void out_kernel(const float* __restrict__ w1, const float* __restrict__ b1v,
                           const float* __restrict__ w2, const float* __restrict__ b2v,
                           const int* __restrict__ batch, float* __restrict__ out) {
    __shared__ float w1s[H * 64];
    __shared__ float w2s[64];
    __shared__ float b1s[64];
    __shared__ float xb[8 * H];
    for (int i = threadIdx.x; i < H * 64; i += blockDim.x) w1s[i] = w1[i];
    if (threadIdx.x < 64) { w2s[threadIdx.x] = w2[threadIdx.x]; b1s[threadIdx.x] = b1v[threadIdx.x]; }
    __syncthreads();
    float ob2 = b2v[0];
    int lane = threadIdx.x & 31;
    int w = threadIdx.x >> 5;
    int wpb = blockDim.x >> 5;
    float* rb = xb + w * H;
    for (int a = blockIdx.x * wpb + w; a < N_ATOMS; a += gridDim.x * wpb) {
        float4 xv = ((const float4*)g_x)[a * 32 + lane];
        ((float4*)rb)[lane] = xv;
        __syncwarp();
        float a0 = b1s[lane], a1 = b1s[lane + 32];
#pragma unroll 4
        for (int k = 0; k < H; k++) {
            float xk = rb[k];
            a0 = fmaf(xk, w1s[k * 64 + lane], a0);
            a1 = fmaf(xk, w1s[k * 64 + lane + 32], a1);
        }
        __syncwarp();
        float part = tanhf(a0) * w2s[lane] + tanhf(a1) * w2s[lane + 32];
#pragma unroll
        for (int off = 16; off; off >>= 1)
            part += __shfl_down_sync(0xffffffffu, part, off);
        if (lane == 0) atomicAdd(&out[batch[a]], part + ob2);
    }
}

// ---------------- host launcher ----------------
extern "C" void kernel_launch(void* const* d_in, const int* in_sizes, int n_in,
                              void* d_out, int out_size) {
    const float* pos        = (const float*)d_in[0];
    const int*   atom_types = (const int*)  d_in[1];
    const int*   edge_index = (const int*)  d_in[2];
    const int*   batch      = (const int*)  d_in[3];
    const float* embedding  = (const float*)d_in[4];
    const float* filt_w1    = (const float*)d_in[5];
    const float* filt_b1    = (const float*)d_in[6];
    const float* filt_w2    = (const float*)d_in[7];
    const float* filt_b2    = (const float*)d_in[8];
    const float* lin1_w     = (const float*)d_in[9];
    const float* lin2_w     = (const float*)d_in[10];
    const float* lin2_b     = (const float*)d_in[11];
    const float* blk_w      = (const float*)d_in[12];
    const float* blk_b      = (const float*)d_in[13];
    const float* out_w1     = (const float*)d_in[14];
    const float* out_b1     = (const float*)d_in[15];
    const float* out_w2     = (const float*)d_in[16];
    const float* out_b2     = (const float*)d_in[17];
    float* out = (float*)d_out;

    const int SM_LIN1 = (H * H + TILE_A * T_STRIDE) * 4;
    const int SM_EDGE = SMF_TOTAL * 4;   // 195072 bytes
    const int SM_UPD  = (2 * H * H + 2 * H + TILE_A * T_STRIDE) * 4;
    cudaFuncSetAttribute(lin1_tiled,      cudaFuncAttributeMaxDynamicSharedMemorySize, SM_LIN1);
    cudaFuncSetAttribute(edge_mma_kernel, cudaFuncAttributeMaxDynamicSharedMemorySize, SM_EDGE);
    cudaFuncSetAttribute(update_tiled,    cudaFuncAttributeMaxDynamicSharedMemorySize, SM_UPD);

    geom_kernel<<<(N_EDGES + 255) / 256, 256>>>(pos, edge_index);
    embed_kernel<<<(N_ATOMS * 32 + 255) / 256, 256>>>(atom_types, embedding);

    for (int b = 0; b < NB; b++) {
        lin1_tiled<<<N_ATILES, 256, SM_LIN1>>>(lin1_w + b * H * H);
        edge_mma_kernel<<<148, 512, SM_EDGE>>>(filt_w1 + b * R * H, filt_b1 + b * H,
                                               filt_w2 + b * H * H, filt_b2 + b * H,
                                               edge_index);
        update_tiled<<<N_ATILES, 256, SM_UPD>>>(lin2_w + b * H * H, lin2_b + b * H,
                                                blk_w + b * H * H, blk_b + b * H);
    }

    zero_out_kernel<<<1, 64>>>(out);
    out_kernel<<<296, 256>>>(out_w1, out_b1, out_w2, out_b2, batch, out);
}